// round 1
// baseline (speedup 1.0000x reference)
#include <cuda_runtime.h>
#include <math.h>

// Problem constants (shapes fixed by the dataset; runtime sizes still read from in_sizes)
#define NP_MAX 100000
#define NA_MAX 50000

// ---------------- device scratch (statically allocated; no runtime allocs) ----------
__device__ float g_h[(size_t)(2 * NP_MAX + NA_MAX) * 256];   // 256 MB: h_cites | h_writes | h_wb
__device__ float g_al_p[(size_t)NP_MAX * 16];                // paper logit precursors (16 cols)
__device__ float g_al_a[(size_t)NA_MAX * 8];                 // author logit precursors (8 cols)
__device__ float g_m[(size_t)(2 * NP_MAX + NA_MAX) * 4];     // segment max per conv/head
__device__ float g_den[(size_t)(2 * NP_MAX + NA_MAX) * 4];   // segment softmax denom
__device__ float g_U[256 * 16 + 256 * 8];                    // folded W@a vectors

// ---------------- helpers ----------------
__device__ __forceinline__ float leaky(float x) { return x > 0.f ? x : 0.2f * x; }

__device__ __forceinline__ void atomicMaxF(float* addr, float v) {
    if (v >= 0.f) atomicMax((int*)addr, __float_as_int(v));
    else          atomicMin((unsigned int*)addr, __float_as_uint(v));
}

__device__ __forceinline__ void red4(float* p, float a, float b, float c, float d) {
    asm volatile("red.global.add.v4.f32 [%0], {%1,%2,%3,%4};"
                 :: "l"(p), "f"(a), "f"(b), "f"(c), "f"(d) : "memory");
}

// ---------------- U = W @ a folding: one tiny CTA ----------------
__global__ void prep_u_kernel(const float* __restrict__ Wc, const float* __restrict__ asc,
                              const float* __restrict__ adc,
                              const float* __restrict__ Ww, const float* __restrict__ asw,
                              const float* __restrict__ adw,
                              const float* __restrict__ Wb, const float* __restrict__ asb,
                              const float* __restrict__ adb) {
    int d = threadIdx.x;  // 256 threads, one per input feature dim
    float* Up = g_U;
    float* Ua = g_U + 256 * 16;
#pragma unroll
    for (int h = 0; h < 4; h++) {
        const float* wc = Wc + d * 256 + h * 64;
        const float* ww = Ww + d * 256 + h * 64;
        const float* wb = Wb + d * 256 + h * 64;
        float s0 = 0.f, s1 = 0.f, s2 = 0.f, s3 = 0.f, s4 = 0.f, s5 = 0.f;
        for (int c = 0; c < 64; c++) {
            s0 += wc[c] * asc[h * 64 + c];   // cites src
            s1 += wc[c] * adc[h * 64 + c];   // cites dst
            s2 += ww[c] * adw[h * 64 + c];   // writes dst (paper)
            s3 += wb[c] * asb[h * 64 + c];   // wb src (paper)
            s4 += ww[c] * asw[h * 64 + c];   // writes src (author)
            s5 += wb[c] * adb[h * 64 + c];   // wb dst (author)
        }
        Up[d * 16 + 0 + h]  = s0;
        Up[d * 16 + 4 + h]  = s1;
        Up[d * 16 + 8 + h]  = s2;
        Up[d * 16 + 12 + h] = s3;
        Ua[d * 8 + 0 + h]   = s4;
        Ua[d * 8 + 4 + h]   = s5;
    }
}

// ---------------- AL = X @ U  (warp per row, ncols in {16,8}) ----------------
__global__ void al_kernel(const float* __restrict__ X, const float* __restrict__ U,
                          float* __restrict__ AL, int N, int ncols) {
    int gw   = (blockIdx.x * blockDim.x + threadIdx.x) >> 5;
    int nw   = (gridDim.x * blockDim.x) >> 5;
    int lane = threadIdx.x & 31;
    for (int row = gw; row < N; row += nw) {
        const float* xr = X + (size_t)row * 256;
        float xf[8];
#pragma unroll
        for (int i = 0; i < 8; i++) xf[i] = xr[lane + 32 * i];
        for (int c = 0; c < ncols; c++) {
            float s = 0.f;
#pragma unroll
            for (int i = 0; i < 8; i++) s += xf[i] * U[(lane + 32 * i) * ncols + c];
#pragma unroll
            for (int o = 16; o > 0; o >>= 1) s += __shfl_xor_sync(0xffffffffu, s, o);
            if (lane == 0) AL[(size_t)row * ncols + c] = s;
        }
    }
}

// ---------------- SGEMM: C[M,256] = A[M,256] @ B[256,256], fp32 -----------------
// 128x128 tile, BK=16, 8x8 per thread, 256 threads.
__global__ __launch_bounds__(256) void sgemm_kernel(const float* __restrict__ A,
                                                    const float* __restrict__ B,
                                                    float* __restrict__ C, int M) {
    __shared__ float As[16][128];
    __shared__ float Bs[16][128];
    const int bm = blockIdx.y * 128;
    const int bn = blockIdx.x * 128;
    const int tid = threadIdx.x;
    const int ty = tid / 16, tx = tid % 16;

    float acc[8][8];
#pragma unroll
    for (int i = 0; i < 8; i++)
#pragma unroll
        for (int j = 0; j < 8; j++) acc[i][j] = 0.f;

    const int arow0 = tid / 4;            // 0..63
    const int acol  = (tid % 4) * 4;      // 0,4,8,12
    const int brow0 = tid / 32;           // 0..7
    const int bcol  = (tid % 32) * 4;     // 0..124

    for (int k0 = 0; k0 < 256; k0 += 16) {
#pragma unroll
        for (int r = 0; r < 2; r++) {
            int row = arow0 + r * 64;
            int grow = bm + row;
            if (grow >= M) grow = M - 1;  // clamp; store predicated later
            float4 v = *(const float4*)(A + (size_t)grow * 256 + k0 + acol);
            As[acol + 0][row] = v.x;
            As[acol + 1][row] = v.y;
            As[acol + 2][row] = v.z;
            As[acol + 3][row] = v.w;
        }
#pragma unroll
        for (int r = 0; r < 2; r++) {
            int row = brow0 + r * 8;
            float4 v = *(const float4*)(B + (size_t)(k0 + row) * 256 + bn + bcol);
            *(float4*)(&Bs[row][bcol]) = v;
        }
        __syncthreads();
#pragma unroll
        for (int kk = 0; kk < 16; kk++) {
            float4 a0 = *(const float4*)(&As[kk][ty * 8]);
            float4 a1 = *(const float4*)(&As[kk][ty * 8 + 4]);
            float4 b0 = *(const float4*)(&Bs[kk][tx * 8]);
            float4 b1 = *(const float4*)(&Bs[kk][tx * 8 + 4]);
            float af[8] = {a0.x, a0.y, a0.z, a0.w, a1.x, a1.y, a1.z, a1.w};
            float bf[8] = {b0.x, b0.y, b0.z, b0.w, b1.x, b1.y, b1.z, b1.w};
#pragma unroll
            for (int i = 0; i < 8; i++)
#pragma unroll
                for (int j = 0; j < 8; j++) acc[i][j] += af[i] * bf[j];
        }
        __syncthreads();
    }

#pragma unroll
    for (int i = 0; i < 8; i++) {
        int grow = bm + ty * 8 + i;
        if (grow < M) {
            float* cp = C + (size_t)grow * 256 + bn + tx * 8;
            *(float4*)(cp)     = make_float4(acc[i][0], acc[i][1], acc[i][2], acc[i][3]);
            *(float4*)(cp + 4) = make_float4(acc[i][4], acc[i][5], acc[i][6], acc[i][7]);
        }
    }
}

// ---------------- init kernels ----------------
__global__ void init_mden_kernel(int total) {
    int i = blockIdx.x * blockDim.x + threadIdx.x;
    if (i < total) {
        g_m[i]   = __int_as_float(0xff800000);  // -inf
        g_den[i] = 0.f;
    }
}

__global__ void init_out_kernel(float* __restrict__ out, const float* __restrict__ bc,
                                const float* __restrict__ bw, const float* __restrict__ bb,
                                int np, int na) {
    size_t i = (size_t)blockIdx.x * blockDim.x + threadIdx.x;
    size_t np_elems = (size_t)np * 256;
    size_t total = np_elems + (size_t)na * 256;
    if (i < total) {
        int c = (int)(i & 255);
        out[i] = (i < np_elems) ? (bc[c] + bw[c]) : bb[c];
    }
}

// ---------------- edge pass A: segment max ----------------
__global__ void edge_max_kernel(const int* __restrict__ edge, int E,
                                const float* __restrict__ als, int ss,
                                const float* __restrict__ ald, int ds,
                                float* __restrict__ m) {
    int t = blockIdx.x * blockDim.x + threadIdx.x;
    if (t >= 4 * E) return;
    int e = t >> 2, h = t & 3;
    int src = edge[e], dst = edge[E + e];
    float lg = leaky(als[(size_t)src * ss + h] + ald[(size_t)dst * ds + h]);
    atomicMaxF(&m[(size_t)dst * 4 + h], lg);
}

// ---------------- edge pass B: softmax denom ----------------
__global__ void edge_sum_kernel(const int* __restrict__ edge, int E,
                                const float* __restrict__ als, int ss,
                                const float* __restrict__ ald, int ds,
                                const float* __restrict__ m, float* __restrict__ den) {
    int t = blockIdx.x * blockDim.x + threadIdx.x;
    if (t >= 4 * E) return;
    int e = t >> 2, h = t & 3;
    int src = edge[e], dst = edge[E + e];
    float lg = leaky(als[(size_t)src * ss + h] + ald[(size_t)dst * ds + h]);
    atomicAdd(&den[(size_t)dst * 4 + h], expf(lg - m[(size_t)dst * 4 + h]));
}

// ---------------- edge pass C: weighted message scatter (warp per edge) ----------
__global__ void edge_msg_kernel(const int* __restrict__ edge, int E,
                                const float* __restrict__ als, int ss,
                                const float* __restrict__ ald, int ds,
                                const float* __restrict__ m, const float* __restrict__ den,
                                const float* __restrict__ h_src, float* __restrict__ out) {
    int w = (blockIdx.x * blockDim.x + threadIdx.x) >> 5;
    if (w >= E) return;
    int lane = threadIdx.x & 31;
    int src = edge[w], dst = edge[E + w];
    int h = lane >> 3;  // 8 lanes per head (8 floats/lane * 8 lanes = 64 ch)
    float lg = leaky(als[(size_t)src * ss + h] + ald[(size_t)dst * ds + h]);
    float wgt = expf(lg - m[(size_t)dst * 4 + h]) / (den[(size_t)dst * 4 + h] + 1e-16f);
    const float4* hs = (const float4*)(h_src + (size_t)src * 256) + lane * 2;
    float* op = out + (size_t)dst * 256 + lane * 8;
    float4 v0 = hs[0], v1 = hs[1];
    red4(op,     v0.x * wgt, v0.y * wgt, v0.z * wgt, v0.w * wgt);
    red4(op + 4, v1.x * wgt, v1.y * wgt, v1.z * wgt, v1.w * wgt);
}

// ---------------- ELU ----------------
__global__ void elu_kernel(float* __restrict__ out, size_t n) {
    size_t i = (size_t)blockIdx.x * blockDim.x + threadIdx.x;
    if (i < n) {
        float v = out[i];
        out[i] = v > 0.f ? v : expm1f(v);
    }
}

// ---------------- host launch ----------------
extern "C" void kernel_launch(void* const* d_in, const int* in_sizes, int n_in,
                              void* d_out, int out_size) {
    const float* x_p  = (const float*)d_in[0];
    const float* x_a  = (const float*)d_in[1];
    const int*   e_c  = (const int*)d_in[2];
    const int*   e_w  = (const int*)d_in[3];
    const int*   e_b  = (const int*)d_in[4];
    const float* W_c  = (const float*)d_in[5];
    const float* as_c = (const float*)d_in[6];
    const float* ad_c = (const float*)d_in[7];
    const float* b_c  = (const float*)d_in[8];
    const float* W_w  = (const float*)d_in[9];
    const float* as_w = (const float*)d_in[10];
    const float* ad_w = (const float*)d_in[11];
    const float* b_w  = (const float*)d_in[12];
    const float* W_b2 = (const float*)d_in[13];
    const float* as_b = (const float*)d_in[14];
    const float* ad_b = (const float*)d_in[15];
    const float* b_b  = (const float*)d_in[16];

    const int np = in_sizes[0] / 256;
    const int na = in_sizes[1] / 256;
    const int Ec = in_sizes[2] / 2;
    const int Ew = in_sizes[3] / 2;
    const int Eb = in_sizes[4] / 2;

    float *h_base, *alp, *ala, *m, *den, *U;
    cudaGetSymbolAddress((void**)&h_base, g_h);
    cudaGetSymbolAddress((void**)&alp, g_al_p);
    cudaGetSymbolAddress((void**)&ala, g_al_a);
    cudaGetSymbolAddress((void**)&m, g_m);
    cudaGetSymbolAddress((void**)&den, g_den);
    cudaGetSymbolAddress((void**)&U, g_U);

    float* h_c = h_base;                               // cites src projection (paper)
    float* h_w = h_base + (size_t)np * 256;            // writes src projection (author)
    float* h_b = h_base + (size_t)(np + na) * 256;     // wb src projection (paper)
    float* out_p = (float*)d_out;
    float* out_a = out_p + (size_t)np * 256;

    float* m_c = m;                      float* d_c = den;
    float* m_w = m + (size_t)np * 4;     float* d_w = den + (size_t)np * 4;
    float* m_b = m + (size_t)2 * np * 4; float* d_b = den + (size_t)2 * np * 4;

    // 1. fold attention vectors through W
    prep_u_kernel<<<1, 256>>>(W_c, as_c, ad_c, W_w, as_w, ad_w, W_b2, as_b, ad_b);

    // 2. logit precursors
    al_kernel<<<1184, 256>>>(x_p, U,            alp, np, 16);
    al_kernel<<<592,  256>>>(x_a, U + 256 * 16, ala, na, 8);

    // 3. src projections (the only full GEMMs needed)
    dim3 gp(2, (np + 127) / 128), ga(2, (na + 127) / 128);
    sgemm_kernel<<<gp, 256>>>(x_p, W_c,  h_c, np);
    sgemm_kernel<<<ga, 256>>>(x_a, W_w,  h_w, na);
    sgemm_kernel<<<gp, 256>>>(x_p, W_b2, h_b, np);

    // 4. init softmax state + output (bias preloaded)
    int mden_total = (2 * np + na) * 4;
    init_mden_kernel<<<(mden_total + 255) / 256, 256>>>(mden_total);
    size_t out_elems = (size_t)(np + na) * 256;
    init_out_kernel<<<(int)((out_elems + 255) / 256), 256>>>(out_p, b_c, b_w, b_b, np, na);

    // 5a. segment max   (cites: p->p, writes: a->p, wb: p->a)
    edge_max_kernel<<<(4 * Ec + 255) / 256, 256>>>(e_c, Ec, alp + 0, 16, alp + 4, 16, m_c);
    edge_max_kernel<<<(4 * Ew + 255) / 256, 256>>>(e_w, Ew, ala + 0, 8,  alp + 8, 16, m_w);
    edge_max_kernel<<<(4 * Eb + 255) / 256, 256>>>(e_b, Eb, alp + 12, 16, ala + 4, 8, m_b);

    // 5b. softmax denominators
    edge_sum_kernel<<<(4 * Ec + 255) / 256, 256>>>(e_c, Ec, alp + 0, 16, alp + 4, 16, m_c, d_c);
    edge_sum_kernel<<<(4 * Ew + 255) / 256, 256>>>(e_w, Ew, ala + 0, 8,  alp + 8, 16, m_w, d_w);
    edge_sum_kernel<<<(4 * Eb + 255) / 256, 256>>>(e_b, Eb, alp + 12, 16, ala + 4, 8, m_b, d_b);

    // 5c. weighted message scatter (warp per edge, red.v4)
    edge_msg_kernel<<<(Ec + 7) / 8, 256>>>(e_c, Ec, alp + 0, 16, alp + 4, 16, m_c, d_c, h_c, out_p);
    edge_msg_kernel<<<(Ew + 7) / 8, 256>>>(e_w, Ew, ala + 0, 8,  alp + 8, 16, m_w, d_w, h_w, out_p);
    edge_msg_kernel<<<(Eb + 7) / 8, 256>>>(e_b, Eb, alp + 12, 16, ala + 4, 8, m_b, d_b, h_b, out_a);

    // 6. ELU epilogue
    elu_kernel<<<(int)((out_elems + 255) / 256), 256>>>(out_p, out_elems);
}

// round 2
// speedup vs baseline: 1.0273x; 1.0273x over previous
#include <cuda_runtime.h>
#include <math.h>

// Problem constants (shapes fixed by the dataset; runtime sizes still read from in_sizes)
#define NP_MAX 100000
#define NA_MAX 50000
#define E_MAX  2100000

// ---------------- device scratch (statically allocated; no runtime allocs) ----------
__device__ float g_h[(size_t)(2 * NP_MAX + NA_MAX) * 256];   // 256 MB: h_cites | h_writes | h_wb
__device__ float g_al_p[(size_t)NP_MAX * 16];                // paper logit precursors (16 cols)
__device__ float g_al_a[(size_t)NA_MAX * 8];                 // author logit precursors (8 cols)
__device__ float g_den[(size_t)(2 * NP_MAX + NA_MAX) * 4];   // segment softmax denom
__device__ float g_ew[(size_t)E_MAX * 4];                    // per-edge exp(logit), 4 heads
__device__ float g_U[256 * 16 + 256 * 8];                    // folded W@a vectors

// ---------------- helpers ----------------
__device__ __forceinline__ float leaky(float x) { return x > 0.f ? x : 0.2f * x; }

__device__ __forceinline__ void red4(float* p, float a, float b, float c, float d) {
    asm volatile("red.global.add.v4.f32 [%0], {%1,%2,%3,%4};"
                 :: "l"(p), "f"(a), "f"(b), "f"(c), "f"(d) : "memory");
}

// ---------------- U = W @ a folding: one tiny CTA ----------------
__global__ void prep_u_kernel(const float* __restrict__ Wc, const float* __restrict__ asc,
                              const float* __restrict__ adc,
                              const float* __restrict__ Ww, const float* __restrict__ asw,
                              const float* __restrict__ adw,
                              const float* __restrict__ Wb, const float* __restrict__ asb,
                              const float* __restrict__ adb) {
    int d = threadIdx.x;  // 256 threads, one per input feature dim
    float* Up = g_U;
    float* Ua = g_U + 256 * 16;
#pragma unroll
    for (int h = 0; h < 4; h++) {
        const float* wc = Wc + d * 256 + h * 64;
        const float* ww = Ww + d * 256 + h * 64;
        const float* wb = Wb + d * 256 + h * 64;
        float s0 = 0.f, s1 = 0.f, s2 = 0.f, s3 = 0.f, s4 = 0.f, s5 = 0.f;
        for (int c = 0; c < 64; c++) {
            s0 += wc[c] * asc[h * 64 + c];   // cites src
            s1 += wc[c] * adc[h * 64 + c];   // cites dst
            s2 += ww[c] * adw[h * 64 + c];   // writes dst (paper)
            s3 += wb[c] * asb[h * 64 + c];   // wb src (paper)
            s4 += ww[c] * asw[h * 64 + c];   // writes src (author)
            s5 += wb[c] * adb[h * 64 + c];   // wb dst (author)
        }
        Up[d * 16 + 0 + h]  = s0;
        Up[d * 16 + 4 + h]  = s1;
        Up[d * 16 + 8 + h]  = s2;
        Up[d * 16 + 12 + h] = s3;
        Ua[d * 8 + 0 + h]   = s4;
        Ua[d * 8 + 4 + h]   = s5;
    }
}

// ---------------- AL = X @ U  (warp per row, ncols in {16,8}) ----------------
__global__ void al_kernel(const float* __restrict__ X, const float* __restrict__ U,
                          float* __restrict__ AL, int N, int ncols) {
    int gw   = (blockIdx.x * blockDim.x + threadIdx.x) >> 5;
    int nw   = (gridDim.x * blockDim.x) >> 5;
    int lane = threadIdx.x & 31;
    for (int row = gw; row < N; row += nw) {
        const float* xr = X + (size_t)row * 256;
        float xf[8];
#pragma unroll
        for (int i = 0; i < 8; i++) xf[i] = xr[lane + 32 * i];
        for (int c = 0; c < ncols; c++) {
            float s = 0.f;
#pragma unroll
            for (int i = 0; i < 8; i++) s += xf[i] * U[(lane + 32 * i) * ncols + c];
#pragma unroll
            for (int o = 16; o > 0; o >>= 1) s += __shfl_xor_sync(0xffffffffu, s, o);
            if (lane == 0) AL[(size_t)row * ncols + c] = s;
        }
    }
}

// ---------------- SGEMM: C[M,256] = A[M,256] @ B[256,256], fp32 -----------------
// 128x128 tile, BK=16, 8x8 per thread, 256 threads.
__global__ __launch_bounds__(256) void sgemm_kernel(const float* __restrict__ A,
                                                    const float* __restrict__ B,
                                                    float* __restrict__ C, int M) {
    __shared__ float As[16][128];
    __shared__ float Bs[16][128];
    const int bm = blockIdx.y * 128;
    const int bn = blockIdx.x * 128;
    const int tid = threadIdx.x;
    const int ty = tid / 16, tx = tid % 16;

    float acc[8][8];
#pragma unroll
    for (int i = 0; i < 8; i++)
#pragma unroll
        for (int j = 0; j < 8; j++) acc[i][j] = 0.f;

    const int arow0 = tid / 4;            // 0..63
    const int acol  = (tid % 4) * 4;      // 0,4,8,12
    const int brow0 = tid / 32;           // 0..7
    const int bcol  = (tid % 32) * 4;     // 0..124

    for (int k0 = 0; k0 < 256; k0 += 16) {
#pragma unroll
        for (int r = 0; r < 2; r++) {
            int row = arow0 + r * 64;
            int grow = bm + row;
            if (grow >= M) grow = M - 1;  // clamp; store predicated later
            float4 v = *(const float4*)(A + (size_t)grow * 256 + k0 + acol);
            As[acol + 0][row] = v.x;
            As[acol + 1][row] = v.y;
            As[acol + 2][row] = v.z;
            As[acol + 3][row] = v.w;
        }
#pragma unroll
        for (int r = 0; r < 2; r++) {
            int row = brow0 + r * 8;
            float4 v = *(const float4*)(B + (size_t)(k0 + row) * 256 + bn + bcol);
            *(float4*)(&Bs[row][bcol]) = v;
        }
        __syncthreads();
#pragma unroll
        for (int kk = 0; kk < 16; kk++) {
            float4 a0 = *(const float4*)(&As[kk][ty * 8]);
            float4 a1 = *(const float4*)(&As[kk][ty * 8 + 4]);
            float4 b0 = *(const float4*)(&Bs[kk][tx * 8]);
            float4 b1 = *(const float4*)(&Bs[kk][tx * 8 + 4]);
            float af[8] = {a0.x, a0.y, a0.z, a0.w, a1.x, a1.y, a1.z, a1.w};
            float bf[8] = {b0.x, b0.y, b0.z, b0.w, b1.x, b1.y, b1.z, b1.w};
#pragma unroll
            for (int i = 0; i < 8; i++)
#pragma unroll
                for (int j = 0; j < 8; j++) acc[i][j] += af[i] * bf[j];
        }
        __syncthreads();
    }

#pragma unroll
    for (int i = 0; i < 8; i++) {
        int grow = bm + ty * 8 + i;
        if (grow < M) {
            float* cp = C + (size_t)grow * 256 + bn + tx * 8;
            *(float4*)(cp)     = make_float4(acc[i][0], acc[i][1], acc[i][2], acc[i][3]);
            *(float4*)(cp + 4) = make_float4(acc[i][4], acc[i][5], acc[i][6], acc[i][7]);
        }
    }
}

// ---------------- init kernels ----------------
__global__ void init_den_kernel(int total) {
    int i = blockIdx.x * blockDim.x + threadIdx.x;
    if (i < total) g_den[i] = 0.f;
}

__global__ void init_out_kernel(float* __restrict__ out, const float* __restrict__ bc,
                                const float* __restrict__ bw, const float* __restrict__ bb,
                                int np, int na) {
    size_t i = (size_t)blockIdx.x * blockDim.x + threadIdx.x;
    size_t np_elems = (size_t)np * 256;
    size_t total = np_elems + (size_t)na * 256;
    if (i < total) {
        int c = (int)(i & 255);
        out[i] = (i < np_elems) ? (bc[c] + bw[c]) : bb[c];
    }
}

// ---------------- edge pass B: exp(logit) + softmax denom (1 thread/edge) --------
// als/ald point at float4-aligned 4-head slices; strides in floats.
__global__ void edge_sum_kernel(const int* __restrict__ edge, int E,
                                const float* __restrict__ als, int ss,
                                const float* __restrict__ ald, int ds,
                                float* __restrict__ den, float* __restrict__ ewbuf) {
    int e = blockIdx.x * blockDim.x + threadIdx.x;
    if (e >= E) return;
    int src = edge[e], dst = edge[E + e];
    float4 s = *(const float4*)(als + (size_t)src * ss);
    float4 d = *(const float4*)(ald + (size_t)dst * ds);
    float4 ew;
    ew.x = expf(leaky(s.x + d.x));
    ew.y = expf(leaky(s.y + d.y));
    ew.z = expf(leaky(s.z + d.z));
    ew.w = expf(leaky(s.w + d.w));
    *(float4*)(ewbuf + (size_t)e * 4) = ew;
    red4(den + (size_t)dst * 4, ew.x, ew.y, ew.z, ew.w);
}

// ---------------- edge pass C: weighted message scatter (warp per edge) ----------
__global__ void edge_msg_kernel(const int* __restrict__ edge, int E,
                                const float* __restrict__ ewbuf,
                                const float* __restrict__ den,
                                const float* __restrict__ h_src, float* __restrict__ out) {
    int w = (blockIdx.x * blockDim.x + threadIdx.x) >> 5;
    if (w >= E) return;
    int lane = threadIdx.x & 31;
    int src = edge[w], dst = edge[E + w];
    float4 ew = *(const float4*)(ewbuf + (size_t)w * 4);   // broadcast
    float4 dn = *(const float4*)(den + (size_t)dst * 4);   // broadcast
    int h = lane >> 3;  // 8 lanes per head
    float eh = (h < 2) ? (h == 0 ? ew.x : ew.y) : (h == 2 ? ew.z : ew.w);
    float dh = (h < 2) ? (h == 0 ? dn.x : dn.y) : (h == 2 ? dn.z : dn.w);
    float wgt = eh / (dh + 1e-16f);
    const float4* hs = (const float4*)(h_src + (size_t)src * 256) + lane * 2;
    float* op = out + (size_t)dst * 256 + lane * 8;
    float4 v0 = hs[0], v1 = hs[1];
    red4(op,     v0.x * wgt, v0.y * wgt, v0.z * wgt, v0.w * wgt);
    red4(op + 4, v1.x * wgt, v1.y * wgt, v1.z * wgt, v1.w * wgt);
}

// ---------------- ELU ----------------
__global__ void elu_kernel(float* __restrict__ out, size_t n) {
    size_t i = (size_t)blockIdx.x * blockDim.x + threadIdx.x;
    if (i < n) {
        float v = out[i];
        out[i] = v > 0.f ? v : expm1f(v);
    }
}

// ---------------- host launch ----------------
extern "C" void kernel_launch(void* const* d_in, const int* in_sizes, int n_in,
                              void* d_out, int out_size) {
    const float* x_p  = (const float*)d_in[0];
    const float* x_a  = (const float*)d_in[1];
    const int*   e_c  = (const int*)d_in[2];
    const int*   e_w  = (const int*)d_in[3];
    const int*   e_b  = (const int*)d_in[4];
    const float* W_c  = (const float*)d_in[5];
    const float* as_c = (const float*)d_in[6];
    const float* ad_c = (const float*)d_in[7];
    const float* b_c  = (const float*)d_in[8];
    const float* W_w  = (const float*)d_in[9];
    const float* as_w = (const float*)d_in[10];
    const float* ad_w = (const float*)d_in[11];
    const float* b_w  = (const float*)d_in[12];
    const float* W_b2 = (const float*)d_in[13];
    const float* as_b = (const float*)d_in[14];
    const float* ad_b = (const float*)d_in[15];
    const float* b_b  = (const float*)d_in[16];

    const int np = in_sizes[0] / 256;
    const int na = in_sizes[1] / 256;
    const int Ec = in_sizes[2] / 2;
    const int Ew = in_sizes[3] / 2;
    const int Eb = in_sizes[4] / 2;

    float *h_base, *alp, *ala, *den, *U, *ew;
    cudaGetSymbolAddress((void**)&h_base, g_h);
    cudaGetSymbolAddress((void**)&alp, g_al_p);
    cudaGetSymbolAddress((void**)&ala, g_al_a);
    cudaGetSymbolAddress((void**)&den, g_den);
    cudaGetSymbolAddress((void**)&U, g_U);
    cudaGetSymbolAddress((void**)&ew, g_ew);

    float* h_c = h_base;                               // cites src projection (paper)
    float* h_w = h_base + (size_t)np * 256;            // writes src projection (author)
    float* h_b = h_base + (size_t)(np + na) * 256;     // wb src projection (paper)
    float* out_p = (float*)d_out;
    float* out_a = out_p + (size_t)np * 256;

    float* d_c = den;
    float* d_w = den + (size_t)np * 4;
    float* d_b = den + (size_t)2 * np * 4;

    float* ew_c = ew;
    float* ew_w = ew + (size_t)Ec * 4;
    float* ew_b = ew + (size_t)(Ec + Ew) * 4;

    // 1. fold attention vectors through W
    prep_u_kernel<<<1, 256>>>(W_c, as_c, ad_c, W_w, as_w, ad_w, W_b2, as_b, ad_b);

    // 2. logit precursors
    al_kernel<<<1184, 256>>>(x_p, U,            alp, np, 16);
    al_kernel<<<592,  256>>>(x_a, U + 256 * 16, ala, na, 8);

    // 3. src projections (the only full GEMMs needed)
    dim3 gp(2, (np + 127) / 128), ga(2, (na + 127) / 128);
    sgemm_kernel<<<gp, 256>>>(x_p, W_c,  h_c, np);
    sgemm_kernel<<<ga, 256>>>(x_a, W_w,  h_w, na);
    sgemm_kernel<<<gp, 256>>>(x_p, W_b2, h_b, np);

    // 4. init softmax denom + output (bias preloaded)
    int den_total = (2 * np + na) * 4;
    init_den_kernel<<<(den_total + 255) / 256, 256>>>(den_total);
    size_t out_elems = (size_t)(np + na) * 256;
    init_out_kernel<<<(int)((out_elems + 255) / 256), 256>>>(out_p, b_c, b_w, b_b, np, na);

    // 5a. exp(logit) + denominators (no max subtraction: logits bounded ~|5|)
    //     cites: p->p, writes: a->p, wb: p->a
    edge_sum_kernel<<<(Ec + 255) / 256, 256>>>(e_c, Ec, alp + 0, 16, alp + 4, 16, d_c, ew_c);
    edge_sum_kernel<<<(Ew + 255) / 256, 256>>>(e_w, Ew, ala + 0, 8,  alp + 8, 16, d_w, ew_w);
    edge_sum_kernel<<<(Eb + 255) / 256, 256>>>(e_b, Eb, alp + 12, 16, ala + 4, 8, d_b, ew_b);

    // 5b. weighted message scatter (warp per edge, red.v4)
    edge_msg_kernel<<<(Ec + 7) / 8, 256>>>(e_c, Ec, ew_c, d_c, h_c, out_p);
    edge_msg_kernel<<<(Ew + 7) / 8, 256>>>(e_w, Ew, ew_w, d_w, h_w, out_p);
    edge_msg_kernel<<<(Eb + 7) / 8, 256>>>(e_b, Eb, ew_b, d_b, h_b, out_a);

    // 6. ELU epilogue
    elu_kernel<<<(int)((out_elems + 255) / 256), 256>>>(out_p, out_elems);
}

// round 3
// speedup vs baseline: 1.1904x; 1.1588x over previous
#include <cuda_runtime.h>
#include <math.h>

// Problem constants (shapes fixed by the dataset; runtime sizes still read from in_sizes)
#define NP_MAX 100000
#define NA_MAX 50000
#define E_MAX  2100000

// ---------------- device scratch (statically allocated; no runtime allocs) ----------
__device__ float g_h[(size_t)(2 * NP_MAX + NA_MAX) * 256];   // 256 MB: h_cites | h_writes | h_wb
__device__ float g_al_p[(size_t)NP_MAX * 16];                // paper logit precursors (16 cols)
__device__ float g_al_a[(size_t)NA_MAX * 8];                 // author logit precursors (8 cols)
__device__ float g_U[256 * 16 + 256 * 8];                    // folded W@a vectors
__device__ int   g_rp[3 * (NP_MAX + 1)];                     // CSR rowptrs (c, w, b)
__device__ int   g_cnt[NP_MAX];                              // degree counts (reused per rel)
__device__ int   g_cur[NP_MAX];                              // scatter cursors (reused per rel)
__device__ int   g_ss[E_MAX];                                // CSR-sorted src indices

// ---------------- helpers ----------------
__device__ __forceinline__ float leaky(float x) { return x > 0.f ? x : 0.2f * x; }

// ---------------- U = W @ a folding: one tiny CTA ----------------
__global__ void prep_u_kernel(const float* __restrict__ Wc, const float* __restrict__ asc,
                              const float* __restrict__ adc,
                              const float* __restrict__ Ww, const float* __restrict__ asw,
                              const float* __restrict__ adw,
                              const float* __restrict__ Wb, const float* __restrict__ asb,
                              const float* __restrict__ adb) {
    int d = threadIdx.x;  // 256 threads, one per input feature dim
    float* Up = g_U;
    float* Ua = g_U + 256 * 16;
#pragma unroll
    for (int h = 0; h < 4; h++) {
        const float* wc = Wc + d * 256 + h * 64;
        const float* ww = Ww + d * 256 + h * 64;
        const float* wb = Wb + d * 256 + h * 64;
        float s0 = 0.f, s1 = 0.f, s2 = 0.f, s3 = 0.f, s4 = 0.f, s5 = 0.f;
        for (int c = 0; c < 64; c++) {
            s0 += wc[c] * asc[h * 64 + c];   // cites src
            s1 += wc[c] * adc[h * 64 + c];   // cites dst
            s2 += ww[c] * adw[h * 64 + c];   // writes dst (paper)
            s3 += wb[c] * asb[h * 64 + c];   // wb src (paper)
            s4 += ww[c] * asw[h * 64 + c];   // writes src (author)
            s5 += wb[c] * adb[h * 64 + c];   // wb dst (author)
        }
        Up[d * 16 + 0 + h]  = s0;
        Up[d * 16 + 4 + h]  = s1;
        Up[d * 16 + 8 + h]  = s2;
        Up[d * 16 + 12 + h] = s3;
        Ua[d * 8 + 0 + h]   = s4;
        Ua[d * 8 + 4 + h]   = s5;
    }
}

// ---------------- AL = X @ U  (warp per row, ncols in {16,8}) ----------------
__global__ void al_kernel(const float* __restrict__ X, const float* __restrict__ U,
                          float* __restrict__ AL, int N, int ncols) {
    int gw   = (blockIdx.x * blockDim.x + threadIdx.x) >> 5;
    int nw   = (gridDim.x * blockDim.x) >> 5;
    int lane = threadIdx.x & 31;
    for (int row = gw; row < N; row += nw) {
        const float* xr = X + (size_t)row * 256;
        float xf[8];
#pragma unroll
        for (int i = 0; i < 8; i++) xf[i] = xr[lane + 32 * i];
        for (int c = 0; c < ncols; c++) {
            float s = 0.f;
#pragma unroll
            for (int i = 0; i < 8; i++) s += xf[i] * U[(lane + 32 * i) * ncols + c];
#pragma unroll
            for (int o = 16; o > 0; o >>= 1) s += __shfl_xor_sync(0xffffffffu, s, o);
            if (lane == 0) AL[(size_t)row * ncols + c] = s;
        }
    }
}

// ---------------- SGEMM: C[M,256] = A[M,256] @ B[256,256], fp32 -----------------
__global__ __launch_bounds__(256) void sgemm_kernel(const float* __restrict__ A,
                                                    const float* __restrict__ B,
                                                    float* __restrict__ C, int M) {
    __shared__ float As[16][128];
    __shared__ float Bs[16][128];
    const int bm = blockIdx.y * 128;
    const int bn = blockIdx.x * 128;
    const int tid = threadIdx.x;
    const int ty = tid / 16, tx = tid % 16;

    float acc[8][8];
#pragma unroll
    for (int i = 0; i < 8; i++)
#pragma unroll
        for (int j = 0; j < 8; j++) acc[i][j] = 0.f;

    const int arow0 = tid / 4;
    const int acol  = (tid % 4) * 4;
    const int brow0 = tid / 32;
    const int bcol  = (tid % 32) * 4;

    for (int k0 = 0; k0 < 256; k0 += 16) {
#pragma unroll
        for (int r = 0; r < 2; r++) {
            int row = arow0 + r * 64;
            int grow = bm + row;
            if (grow >= M) grow = M - 1;
            float4 v = *(const float4*)(A + (size_t)grow * 256 + k0 + acol);
            As[acol + 0][row] = v.x;
            As[acol + 1][row] = v.y;
            As[acol + 2][row] = v.z;
            As[acol + 3][row] = v.w;
        }
#pragma unroll
        for (int r = 0; r < 2; r++) {
            int row = brow0 + r * 8;
            float4 v = *(const float4*)(B + (size_t)(k0 + row) * 256 + bn + bcol);
            *(float4*)(&Bs[row][bcol]) = v;
        }
        __syncthreads();
#pragma unroll
        for (int kk = 0; kk < 16; kk++) {
            float4 a0 = *(const float4*)(&As[kk][ty * 8]);
            float4 a1 = *(const float4*)(&As[kk][ty * 8 + 4]);
            float4 b0 = *(const float4*)(&Bs[kk][tx * 8]);
            float4 b1 = *(const float4*)(&Bs[kk][tx * 8 + 4]);
            float af[8] = {a0.x, a0.y, a0.z, a0.w, a1.x, a1.y, a1.z, a1.w};
            float bf[8] = {b0.x, b0.y, b0.z, b0.w, b1.x, b1.y, b1.z, b1.w};
#pragma unroll
            for (int i = 0; i < 8; i++)
#pragma unroll
                for (int j = 0; j < 8; j++) acc[i][j] += af[i] * bf[j];
        }
        __syncthreads();
    }

#pragma unroll
    for (int i = 0; i < 8; i++) {
        int grow = bm + ty * 8 + i;
        if (grow < M) {
            float* cp = C + (size_t)grow * 256 + bn + tx * 8;
            *(float4*)(cp)     = make_float4(acc[i][0], acc[i][1], acc[i][2], acc[i][3]);
            *(float4*)(cp + 4) = make_float4(acc[i][4], acc[i][5], acc[i][6], acc[i][7]);
        }
    }
}

// ---------------- CSR build ----------------
__global__ void zero_cnt_kernel(int n) {
    int i = blockIdx.x * blockDim.x + threadIdx.x;
    if (i < n) g_cnt[i] = 0;
}

__global__ void hist_kernel(const int* __restrict__ edge, int E) {
    int e = blockIdx.x * blockDim.x + threadIdx.x;
    if (e < E) atomicAdd(&g_cnt[edge[E + e]], 1);
}

// Single-block exclusive scan: counts[0..n) -> rowptr[0..n], cursor[0..n)
__global__ __launch_bounds__(1024) void scan_kernel(int* __restrict__ rowptr,
                                                    int* __restrict__ cursor, int n) {
    __shared__ int sh[1024];
    __shared__ int s_carry;
    int tid = threadIdx.x;
    if (tid == 0) s_carry = 0;
    __syncthreads();
    for (int base = 0; base < n; base += 4096) {
        int idx = base + tid * 4;
        int v0 = (idx + 0 < n) ? g_cnt[idx + 0] : 0;
        int v1 = (idx + 1 < n) ? g_cnt[idx + 1] : 0;
        int v2 = (idx + 2 < n) ? g_cnt[idx + 2] : 0;
        int v3 = (idx + 3 < n) ? g_cnt[idx + 3] : 0;
        int s = v0 + v1 + v2 + v3;
        sh[tid] = s;
        __syncthreads();
#pragma unroll
        for (int off = 1; off < 1024; off <<= 1) {
            int t = (tid >= off) ? sh[tid - off] : 0;
            __syncthreads();
            sh[tid] += t;
            __syncthreads();
        }
        int carry_in = s_carry;
        int excl = sh[tid] - s + carry_in;
        if (idx + 0 < n) { rowptr[idx + 0] = excl; cursor[idx + 0] = excl; } excl += v0;
        if (idx + 1 < n) { rowptr[idx + 1] = excl; cursor[idx + 1] = excl; } excl += v1;
        if (idx + 2 < n) { rowptr[idx + 2] = excl; cursor[idx + 2] = excl; } excl += v2;
        if (idx + 3 < n) { rowptr[idx + 3] = excl; cursor[idx + 3] = excl; }
        __syncthreads();
        if (tid == 0) s_carry = carry_in + sh[1023];
        __syncthreads();
    }
    if (tid == 0) rowptr[n] = s_carry;
}

__global__ void scatter_kernel(const int* __restrict__ edge, int E, int* __restrict__ ss) {
    int e = blockIdx.x * blockDim.x + threadIdx.x;
    if (e >= E) return;
    int pos = atomicAdd(&g_cur[edge[E + e]], 1);
    ss[pos] = edge[e];
}

// ---------------- paper aggregation: cites (p->p) + writes (a->p), fused ----------
// warp per dst row; out = acc_c/den_c + acc_w/den_w + b_c + b_w, then ELU.
__global__ __launch_bounds__(256) void agg_paper_kernel(
    const int* __restrict__ rp_c, const int* __restrict__ ss_c,
    const int* __restrict__ rp_w, const int* __restrict__ ss_w,
    const float* __restrict__ alp, const float* __restrict__ ala,
    const float* __restrict__ h_c, const float* __restrict__ h_w,
    const float* __restrict__ bc, const float* __restrict__ bw,
    float* __restrict__ out, int np)
{
    int d = (blockIdx.x * blockDim.x + threadIdx.x) >> 5;
    if (d >= np) return;
    int lane = threadIdx.x & 31;
    int h = lane >> 3;

    float acc[8] = {0.f, 0.f, 0.f, 0.f, 0.f, 0.f, 0.f, 0.f};
    float res[8];

    // --- cites: dst precursor at alp[d*16+4+h], src at alp[s*16+0+h]
    {
        float ald = __ldg(alp + (size_t)d * 16 + 4 + h);
        float den = 0.f;
        int beg = rp_c[d], end = rp_c[d + 1];
        for (int i = beg; i < end; i++) {
            int s = ss_c[i];
            float ew = __expf(leaky(__ldg(alp + (size_t)s * 16 + h) + ald));
            den += ew;
            const float4* hr = (const float4*)(h_c + (size_t)s * 256) + lane * 2;
            float4 v0 = hr[0], v1 = hr[1];
            acc[0] += ew * v0.x; acc[1] += ew * v0.y; acc[2] += ew * v0.z; acc[3] += ew * v0.w;
            acc[4] += ew * v1.x; acc[5] += ew * v1.y; acc[6] += ew * v1.z; acc[7] += ew * v1.w;
        }
        float inv = 1.f / (den + 1e-16f);
#pragma unroll
        for (int j = 0; j < 8; j++) { res[j] = acc[j] * inv; acc[j] = 0.f; }
    }

    // --- writes: dst precursor at alp[d*16+8+h], src (author) at ala[s*8+0+h]
    {
        float ald = __ldg(alp + (size_t)d * 16 + 8 + h);
        float den = 0.f;
        int beg = rp_w[d], end = rp_w[d + 1];
        for (int i = beg; i < end; i++) {
            int s = ss_w[i];
            float ew = __expf(leaky(__ldg(ala + (size_t)s * 8 + h) + ald));
            den += ew;
            const float4* hr = (const float4*)(h_w + (size_t)s * 256) + lane * 2;
            float4 v0 = hr[0], v1 = hr[1];
            acc[0] += ew * v0.x; acc[1] += ew * v0.y; acc[2] += ew * v0.z; acc[3] += ew * v0.w;
            acc[4] += ew * v1.x; acc[5] += ew * v1.y; acc[6] += ew * v1.z; acc[7] += ew * v1.w;
        }
        float inv = 1.f / (den + 1e-16f);
#pragma unroll
        for (int j = 0; j < 8; j++) res[j] += acc[j] * inv;
    }

    // bias + ELU + write (coalesced)
    int c = lane * 8;
    float4 b0c = *(const float4*)(bc + c), b1c = *(const float4*)(bc + c + 4);
    float4 b0w = *(const float4*)(bw + c), b1w = *(const float4*)(bw + c + 4);
    float bb[8] = {b0c.x + b0w.x, b0c.y + b0w.y, b0c.z + b0w.z, b0c.w + b0w.w,
                   b1c.x + b1w.x, b1c.y + b1w.y, b1c.z + b1w.z, b1c.w + b1w.w};
    float* op = out + (size_t)d * 256 + c;
#pragma unroll
    for (int j = 0; j < 8; j++) {
        float v = res[j] + bb[j];
        res[j] = v > 0.f ? v : expm1f(v);
    }
    *(float4*)(op)     = make_float4(res[0], res[1], res[2], res[3]);
    *(float4*)(op + 4) = make_float4(res[4], res[5], res[6], res[7]);
}

// ---------------- author aggregation: wb (p->a) ----------------
__global__ __launch_bounds__(256) void agg_author_kernel(
    const int* __restrict__ rp_b, const int* __restrict__ ss_b,
    const float* __restrict__ alp, const float* __restrict__ ala,
    const float* __restrict__ h_b, const float* __restrict__ bb,
    float* __restrict__ out, int na)
{
    int d = (blockIdx.x * blockDim.x + threadIdx.x) >> 5;
    if (d >= na) return;
    int lane = threadIdx.x & 31;
    int h = lane >> 3;

    float acc[8] = {0.f, 0.f, 0.f, 0.f, 0.f, 0.f, 0.f, 0.f};
    float ald = __ldg(ala + (size_t)d * 8 + 4 + h);
    float den = 0.f;
    int beg = rp_b[d], end = rp_b[d + 1];
    for (int i = beg; i < end; i++) {
        int s = ss_b[i];
        float ew = __expf(leaky(__ldg(alp + (size_t)s * 16 + 12 + h) + ald));
        den += ew;
        const float4* hr = (const float4*)(h_b + (size_t)s * 256) + lane * 2;
        float4 v0 = hr[0], v1 = hr[1];
        acc[0] += ew * v0.x; acc[1] += ew * v0.y; acc[2] += ew * v0.z; acc[3] += ew * v0.w;
        acc[4] += ew * v1.x; acc[5] += ew * v1.y; acc[6] += ew * v1.z; acc[7] += ew * v1.w;
    }
    float inv = 1.f / (den + 1e-16f);

    int c = lane * 8;
    float4 b0 = *(const float4*)(bb + c), b1 = *(const float4*)(bb + c + 4);
    float bv[8] = {b0.x, b0.y, b0.z, b0.w, b1.x, b1.y, b1.z, b1.w};
    float* op = out + (size_t)d * 256 + c;
    float res[8];
#pragma unroll
    for (int j = 0; j < 8; j++) {
        float v = acc[j] * inv + bv[j];
        res[j] = v > 0.f ? v : expm1f(v);
    }
    *(float4*)(op)     = make_float4(res[0], res[1], res[2], res[3]);
    *(float4*)(op + 4) = make_float4(res[4], res[5], res[6], res[7]);
}

// ---------------- host launch ----------------
extern "C" void kernel_launch(void* const* d_in, const int* in_sizes, int n_in,
                              void* d_out, int out_size) {
    const float* x_p  = (const float*)d_in[0];
    const float* x_a  = (const float*)d_in[1];
    const int*   e_c  = (const int*)d_in[2];
    const int*   e_w  = (const int*)d_in[3];
    const int*   e_b  = (const int*)d_in[4];
    const float* W_c  = (const float*)d_in[5];
    const float* as_c = (const float*)d_in[6];
    const float* ad_c = (const float*)d_in[7];
    const float* b_c  = (const float*)d_in[8];
    const float* W_w  = (const float*)d_in[9];
    const float* as_w = (const float*)d_in[10];
    const float* ad_w = (const float*)d_in[11];
    const float* b_w  = (const float*)d_in[12];
    const float* W_b2 = (const float*)d_in[13];
    const float* as_b = (const float*)d_in[14];
    const float* ad_b = (const float*)d_in[15];
    const float* b_b  = (const float*)d_in[16];

    const int np = in_sizes[0] / 256;
    const int na = in_sizes[1] / 256;
    const int Ec = in_sizes[2] / 2;
    const int Ew = in_sizes[3] / 2;
    const int Eb = in_sizes[4] / 2;

    float *h_base, *alp, *ala, *U;
    int *rp, *ss;
    cudaGetSymbolAddress((void**)&h_base, g_h);
    cudaGetSymbolAddress((void**)&alp, g_al_p);
    cudaGetSymbolAddress((void**)&ala, g_al_a);
    cudaGetSymbolAddress((void**)&U, g_U);
    cudaGetSymbolAddress((void**)&rp, g_rp);
    cudaGetSymbolAddress((void**)&ss, g_ss);

    float* h_c = h_base;                               // cites src projection (paper)
    float* h_w = h_base + (size_t)np * 256;            // writes src projection (author)
    float* h_b = h_base + (size_t)(np + na) * 256;     // wb src projection (paper)
    float* out_p = (float*)d_out;
    float* out_a = out_p + (size_t)np * 256;

    int* rp_c = rp;
    int* rp_w = rp + (NP_MAX + 1);
    int* rp_b = rp + 2 * (NP_MAX + 1);
    int* ss_c = ss;
    int* ss_w = ss + Ec;
    int* ss_b = ss + Ec + Ew;

    int* cur;
    cudaGetSymbolAddress((void**)&cur, g_cur);

    // 1. fold attention vectors through W
    prep_u_kernel<<<1, 256>>>(W_c, as_c, ad_c, W_w, as_w, ad_w, W_b2, as_b, ad_b);

    // 2. logit precursors
    al_kernel<<<1184, 256>>>(x_p, U,            alp, np, 16);
    al_kernel<<<592,  256>>>(x_a, U + 256 * 16, ala, na, 8);

    // 3. CSR build (cites -> np, writes -> np, wb -> na)
    zero_cnt_kernel<<<(np + 255) / 256, 256>>>(np);
    hist_kernel<<<(Ec + 255) / 256, 256>>>(e_c, Ec);
    scan_kernel<<<1, 1024>>>(rp_c, cur, np);
    scatter_kernel<<<(Ec + 255) / 256, 256>>>(e_c, Ec, ss_c);

    zero_cnt_kernel<<<(np + 255) / 256, 256>>>(np);
    hist_kernel<<<(Ew + 255) / 256, 256>>>(e_w, Ew);
    scan_kernel<<<1, 1024>>>(rp_w, cur, np);
    scatter_kernel<<<(Ew + 255) / 256, 256>>>(e_w, Ew, ss_w);

    zero_cnt_kernel<<<(na + 255) / 256, 256>>>(na);
    hist_kernel<<<(Eb + 255) / 256, 256>>>(e_b, Eb);
    scan_kernel<<<1, 1024>>>(rp_b, cur, na);
    scatter_kernel<<<(Eb + 255) / 256, 256>>>(e_b, Eb, ss_b);

    // 4. src projections (the only full GEMMs needed)
    dim3 gp(2, (np + 127) / 128), ga(2, (na + 127) / 128);
    sgemm_kernel<<<gp, 256>>>(x_p, W_c,  h_c, np);
    sgemm_kernel<<<ga, 256>>>(x_a, W_w,  h_w, na);
    sgemm_kernel<<<gp, 256>>>(x_p, W_b2, h_b, np);

    // 5. gather-based aggregation with fused softmax-normalize + bias + ELU
    agg_paper_kernel<<<(np * 32 + 255) / 256, 256>>>(rp_c, ss_c, rp_w, ss_w,
                                                     alp, ala, h_c, h_w,
                                                     b_c, b_w, out_p, np);
    agg_author_kernel<<<(na * 32 + 255) / 256, 256>>>(rp_b, ss_b, alp, ala,
                                                      h_b, b_b, out_a, na);
}

// round 4
// speedup vs baseline: 1.3003x; 1.0923x over previous
#include <cuda_runtime.h>
#include <math.h>

// Problem constants (shapes fixed by the dataset; runtime sizes still read from in_sizes)
#define NP_MAX 100000
#define NA_MAX 50000
#define E_MAX  2100000

// ---------------- device scratch (statically allocated; no runtime allocs) ----------
__device__ float g_h[(size_t)(2 * NP_MAX + NA_MAX) * 256];   // h_cites | h_writes | h_wb
__device__ float g_al_p[(size_t)NP_MAX * 16];                // paper logit precursors (16 cols)
__device__ float g_al_a[(size_t)NA_MAX * 8];                 // author logit precursors (8 cols)
__device__ float g_U[256 * 16 + 256 * 8];                    // folded W@a vectors
__device__ int   g_rp[3 * (NP_MAX + 1)];                     // CSR rowptrs (c, w, b)
__device__ int   g_cnt[2 * NP_MAX + NA_MAX];                 // degree counts (c|w|b)
__device__ int   g_cur[2 * NP_MAX + NA_MAX];                 // scatter cursors (c|w|b)
__device__ int   g_ss[E_MAX];                                // CSR-sorted src indices

// ---------------- helpers ----------------
__device__ __forceinline__ float leaky(float x) { return x > 0.f ? x : 0.2f * x; }

__device__ __forceinline__ unsigned long long pack2(float lo, float hi) {
    unsigned long long r;
    asm("mov.b64 %0, {%1, %2};" : "=l"(r) : "f"(lo), "f"(hi));
    return r;
}
__device__ __forceinline__ void ffma2(unsigned long long& d, unsigned long long a,
                                      unsigned long long b) {
    asm("fma.rn.f32x2 %0, %1, %2, %0;" : "+l"(d) : "l"(a), "l"(b));
}
__device__ __forceinline__ float2 unpack2(unsigned long long v) {
    float2 f;
    asm("mov.b64 {%0, %1}, %2;" : "=f"(f.x), "=f"(f.y) : "l"(v));
    return f;
}

// ---------------- U = W @ a folding: one tiny CTA ----------------
__global__ void prep_u_kernel(const float* __restrict__ Wc, const float* __restrict__ asc,
                              const float* __restrict__ adc,
                              const float* __restrict__ Ww, const float* __restrict__ asw,
                              const float* __restrict__ adw,
                              const float* __restrict__ Wb, const float* __restrict__ asb,
                              const float* __restrict__ adb) {
    int d = threadIdx.x;  // 256 threads, one per input feature dim
    float* Up = g_U;
    float* Ua = g_U + 256 * 16;
#pragma unroll
    for (int h = 0; h < 4; h++) {
        const float* wc = Wc + d * 256 + h * 64;
        const float* ww = Ww + d * 256 + h * 64;
        const float* wb = Wb + d * 256 + h * 64;
        float s0 = 0.f, s1 = 0.f, s2 = 0.f, s3 = 0.f, s4 = 0.f, s5 = 0.f;
        for (int c = 0; c < 64; c++) {
            s0 += wc[c] * asc[h * 64 + c];   // cites src
            s1 += wc[c] * adc[h * 64 + c];   // cites dst
            s2 += ww[c] * adw[h * 64 + c];   // writes dst (paper)
            s3 += wb[c] * asb[h * 64 + c];   // wb src (paper)
            s4 += ww[c] * asw[h * 64 + c];   // writes src (author)
            s5 += wb[c] * adb[h * 64 + c];   // wb dst (author)
        }
        Up[d * 16 + 0 + h]  = s0;
        Up[d * 16 + 4 + h]  = s1;
        Up[d * 16 + 8 + h]  = s2;
        Up[d * 16 + 12 + h] = s3;
        Ua[d * 8 + 0 + h]   = s4;
        Ua[d * 8 + 4 + h]   = s5;
    }
}

// ---------------- AL = X @ U  (warp per row, ncols in {16,8}) ----------------
__global__ void al_kernel(const float* __restrict__ X, const float* __restrict__ U,
                          float* __restrict__ AL, int N, int ncols) {
    int gw   = (blockIdx.x * blockDim.x + threadIdx.x) >> 5;
    int nw   = (gridDim.x * blockDim.x) >> 5;
    int lane = threadIdx.x & 31;
    for (int row = gw; row < N; row += nw) {
        const float* xr = X + (size_t)row * 256;
        float xf[8];
#pragma unroll
        for (int i = 0; i < 8; i++) xf[i] = xr[lane + 32 * i];
        for (int c = 0; c < ncols; c++) {
            float s = 0.f;
#pragma unroll
            for (int i = 0; i < 8; i++) s += xf[i] * U[(lane + 32 * i) * ncols + c];
#pragma unroll
            for (int o = 16; o > 0; o >>= 1) s += __shfl_xor_sync(0xffffffffu, s, o);
            if (lane == 0) AL[(size_t)row * ncols + c] = s;
        }
    }
}

// ---------------- SGEMM: C[M,256] = A[M,256] @ B[256,256], fp32 via f32x2 ---------
// 128x128 tile, BK=16, 8x8 per thread (4 M-pairs x 8 N), double-buffered smem.
__global__ __launch_bounds__(256) void sgemm_kernel(const float* __restrict__ A,
                                                    const float* __restrict__ B,
                                                    float* __restrict__ C, int M) {
    __shared__ float As[2][16][128];
    __shared__ float Bs[2][16][128];
    const int bm = blockIdx.y * 128;
    const int bn = blockIdx.x * 128;
    const int tid = threadIdx.x;
    const int ty = tid / 16, tx = tid % 16;

    unsigned long long acc2[4][8];  // M-pairs (rows 2q,2q+1) x N cols
#pragma unroll
    for (int q = 0; q < 4; q++)
#pragma unroll
        for (int j = 0; j < 8; j++) acc2[q][j] = 0ull;

    const int arow0 = tid / 4;            // 0..63
    const int acol  = (tid % 4) * 4;      // 0,4,8,12
    const int brow0 = tid / 32;           // 0..7
    const int bcol  = (tid % 32) * 4;     // 0..124

    // preload tile 0 into buffer 0
    {
#pragma unroll
        for (int r = 0; r < 2; r++) {
            int row = arow0 + r * 64;
            int grow = bm + row;
            if (grow >= M) grow = M - 1;
            float4 v = *(const float4*)(A + (size_t)grow * 256 + acol);
            As[0][acol + 0][row] = v.x;
            As[0][acol + 1][row] = v.y;
            As[0][acol + 2][row] = v.z;
            As[0][acol + 3][row] = v.w;
        }
#pragma unroll
        for (int r = 0; r < 2; r++) {
            int row = brow0 + r * 8;
            *(float4*)(&Bs[0][row][bcol]) = *(const float4*)(B + (size_t)row * 256 + bn + bcol);
        }
    }
    __syncthreads();

    int buf = 0;
    for (int k0 = 16; k0 <= 256; k0 += 16) {
        const bool has_next = (k0 < 256);
        float4 pa[2], pb[2];
        if (has_next) {
#pragma unroll
            for (int r = 0; r < 2; r++) {
                int row = arow0 + r * 64;
                int grow = bm + row;
                if (grow >= M) grow = M - 1;
                pa[r] = *(const float4*)(A + (size_t)grow * 256 + k0 + acol);
            }
#pragma unroll
            for (int r = 0; r < 2; r++) {
                int row = brow0 + r * 8;
                pb[r] = *(const float4*)(B + (size_t)(k0 + row) * 256 + bn + bcol);
            }
        }
#pragma unroll
        for (int kk = 0; kk < 16; kk++) {
            const unsigned long long* ap =
                (const unsigned long long*)(&As[buf][kk][ty * 8]);
            unsigned long long a2[4];
#pragma unroll
            for (int q = 0; q < 4; q++) a2[q] = ap[q];
            float4 b0 = *(const float4*)(&Bs[buf][kk][tx * 8]);
            float4 b1 = *(const float4*)(&Bs[buf][kk][tx * 8 + 4]);
            unsigned long long b2[8];
            b2[0] = pack2(b0.x, b0.x); b2[1] = pack2(b0.y, b0.y);
            b2[2] = pack2(b0.z, b0.z); b2[3] = pack2(b0.w, b0.w);
            b2[4] = pack2(b1.x, b1.x); b2[5] = pack2(b1.y, b1.y);
            b2[6] = pack2(b1.z, b1.z); b2[7] = pack2(b1.w, b1.w);
#pragma unroll
            for (int q = 0; q < 4; q++)
#pragma unroll
                for (int j = 0; j < 8; j++) ffma2(acc2[q][j], a2[q], b2[j]);
        }
        if (has_next) {
            int nb = buf ^ 1;
#pragma unroll
            for (int r = 0; r < 2; r++) {
                int row = arow0 + r * 64;
                As[nb][acol + 0][row] = pa[r].x;
                As[nb][acol + 1][row] = pa[r].y;
                As[nb][acol + 2][row] = pa[r].z;
                As[nb][acol + 3][row] = pa[r].w;
            }
#pragma unroll
            for (int r = 0; r < 2; r++) {
                int row = brow0 + r * 8;
                *(float4*)(&Bs[nb][row][bcol]) = pb[r];
            }
            __syncthreads();
            buf = nb;
        }
    }

#pragma unroll
    for (int q = 0; q < 4; q++) {
        float2 lo[8];
#pragma unroll
        for (int j = 0; j < 8; j++) lo[j] = unpack2(acc2[q][j]);
        int grow0 = bm + ty * 8 + 2 * q;
        if (grow0 < M) {
            float* cp = C + (size_t)grow0 * 256 + bn + tx * 8;
            *(float4*)(cp)     = make_float4(lo[0].x, lo[1].x, lo[2].x, lo[3].x);
            *(float4*)(cp + 4) = make_float4(lo[4].x, lo[5].x, lo[6].x, lo[7].x);
        }
        if (grow0 + 1 < M) {
            float* cp = C + (size_t)(grow0 + 1) * 256 + bn + tx * 8;
            *(float4*)(cp)     = make_float4(lo[0].y, lo[1].y, lo[2].y, lo[3].y);
            *(float4*)(cp + 4) = make_float4(lo[4].y, lo[5].y, lo[6].y, lo[7].y);
        }
    }
}

// ---------------- CSR build (fused across the 3 relations) ----------------
__global__ void zero_cnt_kernel(int total) {
    int i = blockIdx.x * blockDim.x + threadIdx.x;
    if (i < total) g_cnt[i] = 0;
}

__global__ void hist3_kernel(const int* __restrict__ ec, int Ec,
                             const int* __restrict__ ew, int Ew,
                             const int* __restrict__ eb, int Eb) {
    int t = blockIdx.x * blockDim.x + threadIdx.x;
    if (t < Ec) {
        atomicAdd(&g_cnt[ec[Ec + t]], 1);
    } else if (t < Ec + Ew) {
        int e = t - Ec;
        atomicAdd(&g_cnt[NP_MAX + ew[Ew + e]], 1);
    } else if (t < Ec + Ew + Eb) {
        int e = t - Ec - Ew;
        atomicAdd(&g_cnt[2 * NP_MAX + eb[Eb + e]], 1);
    }
}

// 3 blocks, one per relation; exclusive scan of its count segment.
__global__ __launch_bounds__(1024) void scan3_kernel(int np, int na, int* __restrict__ rp) {
    int rel = blockIdx.x;
    int n = (rel == 2) ? na : np;
    int off = rel * NP_MAX;
    int* rowptr = rp + rel * (NP_MAX + 1);
    const int* cnt = g_cnt + off;
    int* cursor = g_cur + off;

    __shared__ int sh[1024];
    __shared__ int s_carry;
    int tid = threadIdx.x;
    if (tid == 0) s_carry = 0;
    __syncthreads();
    for (int base = 0; base < n; base += 4096) {
        int idx = base + tid * 4;
        int v0 = (idx + 0 < n) ? cnt[idx + 0] : 0;
        int v1 = (idx + 1 < n) ? cnt[idx + 1] : 0;
        int v2 = (idx + 2 < n) ? cnt[idx + 2] : 0;
        int v3 = (idx + 3 < n) ? cnt[idx + 3] : 0;
        int s = v0 + v1 + v2 + v3;
        sh[tid] = s;
        __syncthreads();
#pragma unroll
        for (int o = 1; o < 1024; o <<= 1) {
            int t = (tid >= o) ? sh[tid - o] : 0;
            __syncthreads();
            sh[tid] += t;
            __syncthreads();
        }
        int carry_in = s_carry;
        int excl = sh[tid] - s + carry_in;
        if (idx + 0 < n) { rowptr[idx + 0] = excl; cursor[idx + 0] = excl; } excl += v0;
        if (idx + 1 < n) { rowptr[idx + 1] = excl; cursor[idx + 1] = excl; } excl += v1;
        if (idx + 2 < n) { rowptr[idx + 2] = excl; cursor[idx + 2] = excl; } excl += v2;
        if (idx + 3 < n) { rowptr[idx + 3] = excl; cursor[idx + 3] = excl; }
        __syncthreads();
        if (tid == 0) s_carry = carry_in + sh[1023];
        __syncthreads();
    }
    if (tid == 0) rowptr[n] = s_carry;
}

__global__ void scatter3_kernel(const int* __restrict__ ec, int Ec,
                                const int* __restrict__ ew, int Ew,
                                const int* __restrict__ eb, int Eb) {
    int t = blockIdx.x * blockDim.x + threadIdx.x;
    if (t < Ec) {
        int pos = atomicAdd(&g_cur[ec[Ec + t]], 1);
        g_ss[pos] = ec[t];
    } else if (t < Ec + Ew) {
        int e = t - Ec;
        int pos = atomicAdd(&g_cur[NP_MAX + ew[Ew + e]], 1);
        g_ss[Ec + pos] = ew[e];
    } else if (t < Ec + Ew + Eb) {
        int e = t - Ec - Ew;
        int pos = atomicAdd(&g_cur[2 * NP_MAX + eb[Eb + e]], 1);
        g_ss[Ec + Ew + pos] = eb[e];
    }
}

// ---------------- paper aggregation: cites (p->p) + writes (a->p), fused ----------
// warp per dst row, unroll-2 for MLP.
__global__ __launch_bounds__(256) void agg_paper_kernel(
    const int* __restrict__ rp_c, const int* __restrict__ ss_c,
    const int* __restrict__ rp_w, const int* __restrict__ ss_w,
    const float* __restrict__ alp, const float* __restrict__ ala,
    const float* __restrict__ h_c, const float* __restrict__ h_w,
    const float* __restrict__ bc, const float* __restrict__ bw,
    float* __restrict__ out, int np)
{
    int d = (blockIdx.x * blockDim.x + threadIdx.x) >> 5;
    if (d >= np) return;
    int lane = threadIdx.x & 31;
    int h = lane >> 3;

    float acc[8] = {0.f, 0.f, 0.f, 0.f, 0.f, 0.f, 0.f, 0.f};
    float res[8];

    // --- cites: dst precursor at alp[d*16+4+h], src at alp[s*16+0+h]
    {
        float ald = __ldg(alp + (size_t)d * 16 + 4 + h);
        float den = 0.f;
        int i = rp_c[d], end = rp_c[d + 1];
        for (; i + 1 < end; i += 2) {
            int s0 = __ldg(ss_c + i), s1 = __ldg(ss_c + i + 1);
            float a0 = __ldg(alp + (size_t)s0 * 16 + h);
            float a1 = __ldg(alp + (size_t)s1 * 16 + h);
            const float4* r0 = (const float4*)(h_c + (size_t)s0 * 256) + lane * 2;
            const float4* r1 = (const float4*)(h_c + (size_t)s1 * 256) + lane * 2;
            float4 u0 = r0[0], u1 = r0[1], v0 = r1[0], v1 = r1[1];
            float e0 = __expf(leaky(a0 + ald));
            float e1 = __expf(leaky(a1 + ald));
            den += e0 + e1;
            acc[0] += e0 * u0.x + e1 * v0.x; acc[1] += e0 * u0.y + e1 * v0.y;
            acc[2] += e0 * u0.z + e1 * v0.z; acc[3] += e0 * u0.w + e1 * v0.w;
            acc[4] += e0 * u1.x + e1 * v1.x; acc[5] += e0 * u1.y + e1 * v1.y;
            acc[6] += e0 * u1.z + e1 * v1.z; acc[7] += e0 * u1.w + e1 * v1.w;
        }
        if (i < end) {
            int s = __ldg(ss_c + i);
            float ew = __expf(leaky(__ldg(alp + (size_t)s * 16 + h) + ald));
            den += ew;
            const float4* hr = (const float4*)(h_c + (size_t)s * 256) + lane * 2;
            float4 u0 = hr[0], u1 = hr[1];
            acc[0] += ew * u0.x; acc[1] += ew * u0.y; acc[2] += ew * u0.z; acc[3] += ew * u0.w;
            acc[4] += ew * u1.x; acc[5] += ew * u1.y; acc[6] += ew * u1.z; acc[7] += ew * u1.w;
        }
        float inv = 1.f / (den + 1e-16f);
#pragma unroll
        for (int j = 0; j < 8; j++) { res[j] = acc[j] * inv; acc[j] = 0.f; }
    }

    // --- writes: dst precursor at alp[d*16+8+h], src (author) at ala[s*8+0+h]
    {
        float ald = __ldg(alp + (size_t)d * 16 + 8 + h);
        float den = 0.f;
        int i = rp_w[d], end = rp_w[d + 1];
        for (; i + 1 < end; i += 2) {
            int s0 = __ldg(ss_w + i), s1 = __ldg(ss_w + i + 1);
            float a0 = __ldg(ala + (size_t)s0 * 8 + h);
            float a1 = __ldg(ala + (size_t)s1 * 8 + h);
            const float4* r0 = (const float4*)(h_w + (size_t)s0 * 256) + lane * 2;
            const float4* r1 = (const float4*)(h_w + (size_t)s1 * 256) + lane * 2;
            float4 u0 = r0[0], u1 = r0[1], v0 = r1[0], v1 = r1[1];
            float e0 = __expf(leaky(a0 + ald));
            float e1 = __expf(leaky(a1 + ald));
            den += e0 + e1;
            acc[0] += e0 * u0.x + e1 * v0.x; acc[1] += e0 * u0.y + e1 * v0.y;
            acc[2] += e0 * u0.z + e1 * v0.z; acc[3] += e0 * u0.w + e1 * v0.w;
            acc[4] += e0 * u1.x + e1 * v1.x; acc[5] += e0 * u1.y + e1 * v1.y;
            acc[6] += e0 * u1.z + e1 * v1.z; acc[7] += e0 * u1.w + e1 * v1.w;
        }
        if (i < end) {
            int s = __ldg(ss_w + i);
            float ew = __expf(leaky(__ldg(ala + (size_t)s * 8 + h) + ald));
            den += ew;
            const float4* hr = (const float4*)(h_w + (size_t)s * 256) + lane * 2;
            float4 u0 = hr[0], u1 = hr[1];
            acc[0] += ew * u0.x; acc[1] += ew * u0.y; acc[2] += ew * u0.z; acc[3] += ew * u0.w;
            acc[4] += ew * u1.x; acc[5] += ew * u1.y; acc[6] += ew * u1.z; acc[7] += ew * u1.w;
        }
        float inv = 1.f / (den + 1e-16f);
#pragma unroll
        for (int j = 0; j < 8; j++) res[j] += acc[j] * inv;
    }

    // bias + ELU + write (coalesced)
    int c = lane * 8;
    float4 b0c = *(const float4*)(bc + c), b1c = *(const float4*)(bc + c + 4);
    float4 b0w = *(const float4*)(bw + c), b1w = *(const float4*)(bw + c + 4);
    float bb[8] = {b0c.x + b0w.x, b0c.y + b0w.y, b0c.z + b0w.z, b0c.w + b0w.w,
                   b1c.x + b1w.x, b1c.y + b1w.y, b1c.z + b1w.z, b1c.w + b1w.w};
    float* op = out + (size_t)d * 256 + c;
#pragma unroll
    for (int j = 0; j < 8; j++) {
        float v = res[j] + bb[j];
        res[j] = v > 0.f ? v : expm1f(v);
    }
    *(float4*)(op)     = make_float4(res[0], res[1], res[2], res[3]);
    *(float4*)(op + 4) = make_float4(res[4], res[5], res[6], res[7]);
}

// ---------------- author aggregation: wb (p->a) ----------------
__global__ __launch_bounds__(256) void agg_author_kernel(
    const int* __restrict__ rp_b, const int* __restrict__ ss_b,
    const float* __restrict__ alp, const float* __restrict__ ala,
    const float* __restrict__ h_b, const float* __restrict__ bb,
    float* __restrict__ out, int na)
{
    int d = (blockIdx.x * blockDim.x + threadIdx.x) >> 5;
    if (d >= na) return;
    int lane = threadIdx.x & 31;
    int h = lane >> 3;

    float acc[8] = {0.f, 0.f, 0.f, 0.f, 0.f, 0.f, 0.f, 0.f};
    float ald = __ldg(ala + (size_t)d * 8 + 4 + h);
    float den = 0.f;
    int i = rp_b[d], end = rp_b[d + 1];
    for (; i + 1 < end; i += 2) {
        int s0 = __ldg(ss_b + i), s1 = __ldg(ss_b + i + 1);
        float a0 = __ldg(alp + (size_t)s0 * 16 + 12 + h);
        float a1 = __ldg(alp + (size_t)s1 * 16 + 12 + h);
        const float4* r0 = (const float4*)(h_b + (size_t)s0 * 256) + lane * 2;
        const float4* r1 = (const float4*)(h_b + (size_t)s1 * 256) + lane * 2;
        float4 u0 = r0[0], u1 = r0[1], v0 = r1[0], v1 = r1[1];
        float e0 = __expf(leaky(a0 + ald));
        float e1 = __expf(leaky(a1 + ald));
        den += e0 + e1;
        acc[0] += e0 * u0.x + e1 * v0.x; acc[1] += e0 * u0.y + e1 * v0.y;
        acc[2] += e0 * u0.z + e1 * v0.z; acc[3] += e0 * u0.w + e1 * v0.w;
        acc[4] += e0 * u1.x + e1 * v1.x; acc[5] += e0 * u1.y + e1 * v1.y;
        acc[6] += e0 * u1.z + e1 * v1.z; acc[7] += e0 * u1.w + e1 * v1.w;
    }
    if (i < end) {
        int s = __ldg(ss_b + i);
        float ew = __expf(leaky(__ldg(alp + (size_t)s * 16 + 12 + h) + ald));
        den += ew;
        const float4* hr = (const float4*)(h_b + (size_t)s * 256) + lane * 2;
        float4 u0 = hr[0], u1 = hr[1];
        acc[0] += ew * u0.x; acc[1] += ew * u0.y; acc[2] += ew * u0.z; acc[3] += ew * u0.w;
        acc[4] += ew * u1.x; acc[5] += ew * u1.y; acc[6] += ew * u1.z; acc[7] += ew * u1.w;
    }
    float inv = 1.f / (den + 1e-16f);

    int c = lane * 8;
    float4 b0 = *(const float4*)(bb + c), b1 = *(const float4*)(bb + c + 4);
    float bv[8] = {b0.x, b0.y, b0.z, b0.w, b1.x, b1.y, b1.z, b1.w};
    float* op = out + (size_t)d * 256 + c;
    float res[8];
#pragma unroll
    for (int j = 0; j < 8; j++) {
        float v = acc[j] * inv + bv[j];
        res[j] = v > 0.f ? v : expm1f(v);
    }
    *(float4*)(op)     = make_float4(res[0], res[1], res[2], res[3]);
    *(float4*)(op + 4) = make_float4(res[4], res[5], res[6], res[7]);
}

// ---------------- host launch ----------------
extern "C" void kernel_launch(void* const* d_in, const int* in_sizes, int n_in,
                              void* d_out, int out_size) {
    const float* x_p  = (const float*)d_in[0];
    const float* x_a  = (const float*)d_in[1];
    const int*   e_c  = (const int*)d_in[2];
    const int*   e_w  = (const int*)d_in[3];
    const int*   e_b  = (const int*)d_in[4];
    const float* W_c  = (const float*)d_in[5];
    const float* as_c = (const float*)d_in[6];
    const float* ad_c = (const float*)d_in[7];
    const float* b_c  = (const float*)d_in[8];
    const float* W_w  = (const float*)d_in[9];
    const float* as_w = (const float*)d_in[10];
    const float* ad_w = (const float*)d_in[11];
    const float* b_w  = (const float*)d_in[12];
    const float* W_b2 = (const float*)d_in[13];
    const float* as_b = (const float*)d_in[14];
    const float* ad_b = (const float*)d_in[15];
    const float* b_b  = (const float*)d_in[16];

    const int np = in_sizes[0] / 256;
    const int na = in_sizes[1] / 256;
    const int Ec = in_sizes[2] / 2;
    const int Ew = in_sizes[3] / 2;
    const int Eb = in_sizes[4] / 2;

    float *h_base, *alp, *ala, *U;
    int *rp, *ss;
    cudaGetSymbolAddress((void**)&h_base, g_h);
    cudaGetSymbolAddress((void**)&alp, g_al_p);
    cudaGetSymbolAddress((void**)&ala, g_al_a);
    cudaGetSymbolAddress((void**)&U, g_U);
    cudaGetSymbolAddress((void**)&rp, g_rp);
    cudaGetSymbolAddress((void**)&ss, g_ss);

    float* h_c = h_base;                               // cites src projection (paper)
    float* h_w = h_base + (size_t)np * 256;            // writes src projection (author)
    float* h_b = h_base + (size_t)(np + na) * 256;     // wb src projection (paper)
    float* out_p = (float*)d_out;
    float* out_a = out_p + (size_t)np * 256;

    int* rp_c = rp;
    int* rp_w = rp + (NP_MAX + 1);
    int* rp_b = rp + 2 * (NP_MAX + 1);
    int* ss_c = ss;
    int* ss_w = ss + Ec;
    int* ss_b = ss + Ec + Ew;

    // 1. fold attention vectors through W
    prep_u_kernel<<<1, 256>>>(W_c, as_c, ad_c, W_w, as_w, ad_w, W_b2, as_b, ad_b);

    // 2. logit precursors
    al_kernel<<<1184, 256>>>(x_p, U,            alp, np, 16);
    al_kernel<<<592,  256>>>(x_a, U + 256 * 16, ala, na, 8);

    // 3. CSR build (fused across relations)
    int cnt_total = 2 * NP_MAX + NA_MAX;
    int Etot = Ec + Ew + Eb;
    zero_cnt_kernel<<<(cnt_total + 255) / 256, 256>>>(cnt_total);
    hist3_kernel<<<(Etot + 255) / 256, 256>>>(e_c, Ec, e_w, Ew, e_b, Eb);
    scan3_kernel<<<3, 1024>>>(np, na, rp);
    scatter3_kernel<<<(Etot + 255) / 256, 256>>>(e_c, Ec, e_w, Ew, e_b, Eb);

    // 4. src projections (f32x2 packed GEMMs)
    dim3 gp(2, (np + 127) / 128), ga(2, (na + 127) / 128);
    sgemm_kernel<<<gp, 256>>>(x_p, W_c,  h_c, np);
    sgemm_kernel<<<ga, 256>>>(x_a, W_w,  h_w, na);
    sgemm_kernel<<<gp, 256>>>(x_p, W_b2, h_b, np);

    // 5. gather-based aggregation with fused softmax-normalize + bias + ELU
    agg_paper_kernel<<<(np * 32 + 255) / 256, 256>>>(rp_c, ss_c, rp_w, ss_w,
                                                     alp, ala, h_c, h_w,
                                                     b_c, b_w, out_p, np);
    agg_author_kernel<<<(na * 32 + 255) / 256, 256>>>(rp_b, ss_b, alp, ala,
                                                      h_b, b_b, out_a, na);
}

// round 5
// speedup vs baseline: 1.6993x; 1.3068x over previous
#include <cuda_runtime.h>
#include <cuda_fp16.h>
#include <math.h>

// Problem constants (shapes fixed by the dataset; runtime sizes still read from in_sizes)
#define NP_MAX 100000
#define NA_MAX 50000
#define E_MAX  2100000

// ---------------- device scratch (statically allocated; no runtime allocs) ----------
__device__ __half g_h[(size_t)(2 * NP_MAX + NA_MAX) * 256]; // h_cites | h_writes | h_wb (fp16)
__device__ float g_al_p[(size_t)NP_MAX * 16];               // paper logit precursors (16 cols)
__device__ float g_al_a[(size_t)NA_MAX * 8];                // author logit precursors (8 cols)
__device__ float g_U[256 * 16 + 256 * 8];                   // folded W@a vectors
__device__ int   g_rp[3 * (NP_MAX + 1)];                    // CSR rowptrs (c, w, b)
__device__ int   g_cnt[2 * NP_MAX + NA_MAX];                // degree counts (c|w|b)
__device__ int   g_cur[2 * NP_MAX + NA_MAX];                // scatter cursors (c|w|b)
__device__ int   g_ss[E_MAX];                               // CSR-sorted src indices

// ---------------- helpers ----------------
__device__ __forceinline__ float leaky(float x) { return x > 0.f ? x : 0.2f * x; }

__device__ __forceinline__ unsigned to_tf32(float f) {
    unsigned u;
    asm("cvt.rna.tf32.f32 %0, %1;" : "=r"(u) : "f"(f));
    return u;
}

__device__ __forceinline__ void mma_tf32(float* c, const unsigned* a, const unsigned* b) {
    asm("mma.sync.aligned.m16n8k8.row.col.f32.tf32.tf32.f32 "
        "{%0,%1,%2,%3},{%4,%5,%6,%7},{%8,%9},{%0,%1,%2,%3};"
        : "+f"(c[0]), "+f"(c[1]), "+f"(c[2]), "+f"(c[3])
        : "r"(a[0]), "r"(a[1]), "r"(a[2]), "r"(a[3]), "r"(b[0]), "r"(b[1]));
}

// unpack 8 consecutive halves (one uint4) into fp32
__device__ __forceinline__ void h8_to_f(uint4 v, float* f) {
    float2 t;
    t = __half22float2(*(__half2*)&v.x); f[0] = t.x; f[1] = t.y;
    t = __half22float2(*(__half2*)&v.y); f[2] = t.x; f[3] = t.y;
    t = __half22float2(*(__half2*)&v.z); f[4] = t.x; f[5] = t.y;
    t = __half22float2(*(__half2*)&v.w); f[6] = t.x; f[7] = t.y;
}

// ---------------- U = W @ a folding: one tiny CTA ----------------
__global__ void prep_u_kernel(const float* __restrict__ Wc, const float* __restrict__ asc,
                              const float* __restrict__ adc,
                              const float* __restrict__ Ww, const float* __restrict__ asw,
                              const float* __restrict__ adw,
                              const float* __restrict__ Wb, const float* __restrict__ asb,
                              const float* __restrict__ adb) {
    int d = threadIdx.x;  // 256 threads, one per input feature dim
    float* Up = g_U;
    float* Ua = g_U + 256 * 16;
#pragma unroll
    for (int h = 0; h < 4; h++) {
        const float* wc = Wc + d * 256 + h * 64;
        const float* ww = Ww + d * 256 + h * 64;
        const float* wb = Wb + d * 256 + h * 64;
        float s0 = 0.f, s1 = 0.f, s2 = 0.f, s3 = 0.f, s4 = 0.f, s5 = 0.f;
        for (int c = 0; c < 64; c++) {
            s0 += wc[c] * asc[h * 64 + c];   // cites src
            s1 += wc[c] * adc[h * 64 + c];   // cites dst
            s2 += ww[c] * adw[h * 64 + c];   // writes dst (paper)
            s3 += wb[c] * asb[h * 64 + c];   // wb src (paper)
            s4 += ww[c] * asw[h * 64 + c];   // writes src (author)
            s5 += wb[c] * adb[h * 64 + c];   // wb dst (author)
        }
        Up[d * 16 + 0 + h]  = s0;
        Up[d * 16 + 4 + h]  = s1;
        Up[d * 16 + 8 + h]  = s2;
        Up[d * 16 + 12 + h] = s3;
        Ua[d * 8 + 0 + h]   = s4;
        Ua[d * 8 + 4 + h]   = s5;
    }
}

// ---------------- AL = X @ U  (warp per row, ncols in {16,8}) ----------------
__global__ void al_kernel(const float* __restrict__ X, const float* __restrict__ U,
                          float* __restrict__ AL, int N, int ncols) {
    int gw   = (blockIdx.x * blockDim.x + threadIdx.x) >> 5;
    int nw   = (gridDim.x * blockDim.x) >> 5;
    int lane = threadIdx.x & 31;
    for (int row = gw; row < N; row += nw) {
        const float* xr = X + (size_t)row * 256;
        float xf[8];
#pragma unroll
        for (int i = 0; i < 8; i++) xf[i] = xr[lane + 32 * i];
        for (int c = 0; c < ncols; c++) {
            float s = 0.f;
#pragma unroll
            for (int i = 0; i < 8; i++) s += xf[i] * U[(lane + 32 * i) * ncols + c];
#pragma unroll
            for (int o = 16; o > 0; o >>= 1) s += __shfl_xor_sync(0xffffffffu, s, o);
            if (lane == 0) AL[(size_t)row * ncols + c] = s;
        }
    }
}

// ---------------- tf32 GEMM: C[M,256](fp16) = A[M,256] @ B[256,256] ----------------
// 128x128 tile, BK=16, 8 warps (4x2), warp tile 32x64, mma m16n8k8, double-buffered.
__global__ __launch_bounds__(256) void gemm_tf32_kernel(const float* __restrict__ A,
                                                        const float* __restrict__ B,
                                                        __half* __restrict__ C, int M) {
    __shared__ float As[2][16][132];
    __shared__ float Bs[2][16][132];
    const int bm = blockIdx.y * 128;
    const int bn = blockIdx.x * 128;
    const int tid = threadIdx.x;
    const int wid = tid >> 5, lane = tid & 31;
    const int warpM = wid & 3, warpN = wid >> 2;
    const int row0 = warpM * 32;        // warp's M offset within tile
    const int nb0  = warpN * 64;        // warp's N offset within tile
    const int g = lane >> 2, tig = lane & 3;

    float acc[2][8][4];
#pragma unroll
    for (int mi = 0; mi < 2; mi++)
#pragma unroll
        for (int ni = 0; ni < 8; ni++)
#pragma unroll
            for (int r = 0; r < 4; r++) acc[mi][ni][r] = 0.f;

    const int arow0 = tid / 4;            // 0..63
    const int acol  = (tid % 4) * 4;      // 0,4,8,12
    const int brow0 = tid / 32;           // 0..7
    const int bcol  = (tid % 32) * 4;     // 0..124

    // preload tile 0 into buffer 0
    {
#pragma unroll
        for (int r = 0; r < 2; r++) {
            int row = arow0 + r * 64;
            int grow = bm + row;
            if (grow >= M) grow = M - 1;
            float4 v = *(const float4*)(A + (size_t)grow * 256 + acol);
            As[0][acol + 0][row] = v.x;
            As[0][acol + 1][row] = v.y;
            As[0][acol + 2][row] = v.z;
            As[0][acol + 3][row] = v.w;
        }
#pragma unroll
        for (int r = 0; r < 2; r++) {
            int row = brow0 + r * 8;
            *(float4*)(&Bs[0][row][bcol]) = *(const float4*)(B + (size_t)row * 256 + bn + bcol);
        }
    }
    __syncthreads();

    int buf = 0;
    for (int k0 = 16; k0 <= 256; k0 += 16) {
        const bool has_next = (k0 < 256);
        float4 pa[2], pb[2];
        if (has_next) {
#pragma unroll
            for (int r = 0; r < 2; r++) {
                int row = arow0 + r * 64;
                int grow = bm + row;
                if (grow >= M) grow = M - 1;
                pa[r] = *(const float4*)(A + (size_t)grow * 256 + k0 + acol);
            }
#pragma unroll
            for (int r = 0; r < 2; r++) {
                int row = brow0 + r * 8;
                pb[r] = *(const float4*)(B + (size_t)(k0 + row) * 256 + bn + bcol);
            }
        }
#pragma unroll
        for (int ks = 0; ks < 16; ks += 8) {
            unsigned af[2][4];
#pragma unroll
            for (int mi = 0; mi < 2; mi++) {
                int r = row0 + mi * 16 + g;
                af[mi][0] = to_tf32(As[buf][ks + tig][r]);
                af[mi][1] = to_tf32(As[buf][ks + tig][r + 8]);
                af[mi][2] = to_tf32(As[buf][ks + tig + 4][r]);
                af[mi][3] = to_tf32(As[buf][ks + tig + 4][r + 8]);
            }
            unsigned bf[8][2];
#pragma unroll
            for (int ni = 0; ni < 8; ni++) {
                int c = nb0 + ni * 8 + g;
                bf[ni][0] = to_tf32(Bs[buf][ks + tig][c]);
                bf[ni][1] = to_tf32(Bs[buf][ks + tig + 4][c]);
            }
#pragma unroll
            for (int mi = 0; mi < 2; mi++)
#pragma unroll
                for (int ni = 0; ni < 8; ni++)
                    mma_tf32(acc[mi][ni], af[mi], bf[ni]);
        }
        if (has_next) {
            int nbuf = buf ^ 1;
#pragma unroll
            for (int r = 0; r < 2; r++) {
                int row = arow0 + r * 64;
                As[nbuf][acol + 0][row] = pa[r].x;
                As[nbuf][acol + 1][row] = pa[r].y;
                As[nbuf][acol + 2][row] = pa[r].z;
                As[nbuf][acol + 3][row] = pa[r].w;
            }
#pragma unroll
            for (int r = 0; r < 2; r++) {
                int row = brow0 + r * 8;
                *(float4*)(&Bs[nbuf][row][bcol]) = pb[r];
            }
            __syncthreads();
            buf = nbuf;
        }
    }

    // epilogue: fp16 stores
#pragma unroll
    for (int mi = 0; mi < 2; mi++) {
        int row = bm + row0 + mi * 16 + g;
#pragma unroll
        for (int ni = 0; ni < 8; ni++) {
            int col = bn + nb0 + ni * 8 + 2 * tig;
            if (row < M)
                *(__half2*)(C + (size_t)row * 256 + col) =
                    __floats2half2_rn(acc[mi][ni][0], acc[mi][ni][1]);
            if (row + 8 < M)
                *(__half2*)(C + (size_t)(row + 8) * 256 + col) =
                    __floats2half2_rn(acc[mi][ni][2], acc[mi][ni][3]);
        }
    }
}

// ---------------- CSR build (fused across the 3 relations) ----------------
__global__ void zero_cnt_kernel(int total) {
    int i = blockIdx.x * blockDim.x + threadIdx.x;
    if (i < total) g_cnt[i] = 0;
}

__global__ void hist3_kernel(const int* __restrict__ ec, int Ec,
                             const int* __restrict__ ew, int Ew,
                             const int* __restrict__ eb, int Eb) {
    int t = blockIdx.x * blockDim.x + threadIdx.x;
    if (t < Ec) {
        atomicAdd(&g_cnt[ec[Ec + t]], 1);
    } else if (t < Ec + Ew) {
        int e = t - Ec;
        atomicAdd(&g_cnt[NP_MAX + ew[Ew + e]], 1);
    } else if (t < Ec + Ew + Eb) {
        int e = t - Ec - Ew;
        atomicAdd(&g_cnt[2 * NP_MAX + eb[Eb + e]], 1);
    }
}

// 3 blocks, one per relation; exclusive scan of its count segment.
__global__ __launch_bounds__(1024) void scan3_kernel(int np, int na, int* __restrict__ rp) {
    int rel = blockIdx.x;
    int n = (rel == 2) ? na : np;
    int off = rel * NP_MAX;
    int* rowptr = rp + rel * (NP_MAX + 1);
    const int* cnt = g_cnt + off;
    int* cursor = g_cur + off;

    __shared__ int sh[1024];
    __shared__ int s_carry;
    int tid = threadIdx.x;
    if (tid == 0) s_carry = 0;
    __syncthreads();
    for (int base = 0; base < n; base += 4096) {
        int idx = base + tid * 4;
        int v0 = (idx + 0 < n) ? cnt[idx + 0] : 0;
        int v1 = (idx + 1 < n) ? cnt[idx + 1] : 0;
        int v2 = (idx + 2 < n) ? cnt[idx + 2] : 0;
        int v3 = (idx + 3 < n) ? cnt[idx + 3] : 0;
        int s = v0 + v1 + v2 + v3;
        sh[tid] = s;
        __syncthreads();
#pragma unroll
        for (int o = 1; o < 1024; o <<= 1) {
            int t = (tid >= o) ? sh[tid - o] : 0;
            __syncthreads();
            sh[tid] += t;
            __syncthreads();
        }
        int carry_in = s_carry;
        int excl = sh[tid] - s + carry_in;
        if (idx + 0 < n) { rowptr[idx + 0] = excl; cursor[idx + 0] = excl; } excl += v0;
        if (idx + 1 < n) { rowptr[idx + 1] = excl; cursor[idx + 1] = excl; } excl += v1;
        if (idx + 2 < n) { rowptr[idx + 2] = excl; cursor[idx + 2] = excl; } excl += v2;
        if (idx + 3 < n) { rowptr[idx + 3] = excl; cursor[idx + 3] = excl; }
        __syncthreads();
        if (tid == 0) s_carry = carry_in + sh[1023];
        __syncthreads();
    }
    if (tid == 0) rowptr[n] = s_carry;
}

__global__ void scatter3_kernel(const int* __restrict__ ec, int Ec,
                                const int* __restrict__ ew, int Ew,
                                const int* __restrict__ eb, int Eb) {
    int t = blockIdx.x * blockDim.x + threadIdx.x;
    if (t < Ec) {
        int pos = atomicAdd(&g_cur[ec[Ec + t]], 1);
        g_ss[pos] = ec[t];
    } else if (t < Ec + Ew) {
        int e = t - Ec;
        int pos = atomicAdd(&g_cur[NP_MAX + ew[Ew + e]], 1);
        g_ss[Ec + pos] = ew[e];
    } else if (t < Ec + Ew + Eb) {
        int e = t - Ec - Ew;
        int pos = atomicAdd(&g_cur[2 * NP_MAX + eb[Eb + e]], 1);
        g_ss[Ec + Ew + pos] = eb[e];
    }
}

// ---------------- paper aggregation: cites (p->p) + writes (a->p), fused ----------
// warp per dst row, unroll-2 for MLP, fp16 h rows.
__global__ __launch_bounds__(256) void agg_paper_kernel(
    const int* __restrict__ rp_c, const int* __restrict__ ss_c,
    const int* __restrict__ rp_w, const int* __restrict__ ss_w,
    const float* __restrict__ alp, const float* __restrict__ ala,
    const __half* __restrict__ h_c, const __half* __restrict__ h_w,
    const float* __restrict__ bc, const float* __restrict__ bw,
    float* __restrict__ out, int np)
{
    int d = (blockIdx.x * blockDim.x + threadIdx.x) >> 5;
    if (d >= np) return;
    int lane = threadIdx.x & 31;
    int h = lane >> 3;

    float acc[8] = {0.f, 0.f, 0.f, 0.f, 0.f, 0.f, 0.f, 0.f};
    float res[8];
    float f0[8], f1[8];

    // --- cites: dst precursor at alp[d*16+4+h], src at alp[s*16+0+h]
    {
        float ald = __ldg(alp + (size_t)d * 16 + 4 + h);
        float den = 0.f;
        int i = rp_c[d], end = rp_c[d + 1];
        for (; i + 1 < end; i += 2) {
            int s0 = __ldg(ss_c + i), s1 = __ldg(ss_c + i + 1);
            float a0 = __ldg(alp + (size_t)s0 * 16 + h);
            float a1 = __ldg(alp + (size_t)s1 * 16 + h);
            uint4 r0 = *((const uint4*)(h_c + (size_t)s0 * 256) + lane);
            uint4 r1 = *((const uint4*)(h_c + (size_t)s1 * 256) + lane);
            float e0 = __expf(leaky(a0 + ald));
            float e1 = __expf(leaky(a1 + ald));
            den += e0 + e1;
            h8_to_f(r0, f0); h8_to_f(r1, f1);
#pragma unroll
            for (int j = 0; j < 8; j++) acc[j] += e0 * f0[j] + e1 * f1[j];
        }
        if (i < end) {
            int s = __ldg(ss_c + i);
            float ew = __expf(leaky(__ldg(alp + (size_t)s * 16 + h) + ald));
            den += ew;
            uint4 r0 = *((const uint4*)(h_c + (size_t)s * 256) + lane);
            h8_to_f(r0, f0);
#pragma unroll
            for (int j = 0; j < 8; j++) acc[j] += ew * f0[j];
        }
        float inv = 1.f / (den + 1e-16f);
#pragma unroll
        for (int j = 0; j < 8; j++) { res[j] = acc[j] * inv; acc[j] = 0.f; }
    }

    // --- writes: dst precursor at alp[d*16+8+h], src (author) at ala[s*8+0+h]
    {
        float ald = __ldg(alp + (size_t)d * 16 + 8 + h);
        float den = 0.f;
        int i = rp_w[d], end = rp_w[d + 1];
        for (; i + 1 < end; i += 2) {
            int s0 = __ldg(ss_w + i), s1 = __ldg(ss_w + i + 1);
            float a0 = __ldg(ala + (size_t)s0 * 8 + h);
            float a1 = __ldg(ala + (size_t)s1 * 8 + h);
            uint4 r0 = *((const uint4*)(h_w + (size_t)s0 * 256) + lane);
            uint4 r1 = *((const uint4*)(h_w + (size_t)s1 * 256) + lane);
            float e0 = __expf(leaky(a0 + ald));
            float e1 = __expf(leaky(a1 + ald));
            den += e0 + e1;
            h8_to_f(r0, f0); h8_to_f(r1, f1);
#pragma unroll
            for (int j = 0; j < 8; j++) acc[j] += e0 * f0[j] + e1 * f1[j];
        }
        if (i < end) {
            int s = __ldg(ss_w + i);
            float ew = __expf(leaky(__ldg(ala + (size_t)s * 8 + h) + ald));
            den += ew;
            uint4 r0 = *((const uint4*)(h_w + (size_t)s * 256) + lane);
            h8_to_f(r0, f0);
#pragma unroll
            for (int j = 0; j < 8; j++) acc[j] += ew * f0[j];
        }
        float inv = 1.f / (den + 1e-16f);
#pragma unroll
        for (int j = 0; j < 8; j++) res[j] += acc[j] * inv;
    }

    // bias + ELU + write (coalesced)
    int c = lane * 8;
    float4 b0c = *(const float4*)(bc + c), b1c = *(const float4*)(bc + c + 4);
    float4 b0w = *(const float4*)(bw + c), b1w = *(const float4*)(bw + c + 4);
    float bb[8] = {b0c.x + b0w.x, b0c.y + b0w.y, b0c.z + b0w.z, b0c.w + b0w.w,
                   b1c.x + b1w.x, b1c.y + b1w.y, b1c.z + b1w.z, b1c.w + b1w.w};
    float* op = out + (size_t)d * 256 + c;
#pragma unroll
    for (int j = 0; j < 8; j++) {
        float v = res[j] + bb[j];
        res[j] = v > 0.f ? v : expm1f(v);
    }
    *(float4*)(op)     = make_float4(res[0], res[1], res[2], res[3]);
    *(float4*)(op + 4) = make_float4(res[4], res[5], res[6], res[7]);
}

// ---------------- author aggregation: wb (p->a) ----------------
__global__ __launch_bounds__(256) void agg_author_kernel(
    const int* __restrict__ rp_b, const int* __restrict__ ss_b,
    const float* __restrict__ alp, const float* __restrict__ ala,
    const __half* __restrict__ h_b, const float* __restrict__ bb,
    float* __restrict__ out, int na)
{
    int d = (blockIdx.x * blockDim.x + threadIdx.x) >> 5;
    if (d >= na) return;
    int lane = threadIdx.x & 31;
    int h = lane >> 3;

    float acc[8] = {0.f, 0.f, 0.f, 0.f, 0.f, 0.f, 0.f, 0.f};
    float f0[8], f1[8];
    float ald = __ldg(ala + (size_t)d * 8 + 4 + h);
    float den = 0.f;
    int i = rp_b[d], end = rp_b[d + 1];
    for (; i + 1 < end; i += 2) {
        int s0 = __ldg(ss_b + i), s1 = __ldg(ss_b + i + 1);
        float a0 = __ldg(alp + (size_t)s0 * 16 + 12 + h);
        float a1 = __ldg(alp + (size_t)s1 * 16 + 12 + h);
        uint4 r0 = *((const uint4*)(h_b + (size_t)s0 * 256) + lane);
        uint4 r1 = *((const uint4*)(h_b + (size_t)s1 * 256) + lane);
        float e0 = __expf(leaky(a0 + ald));
        float e1 = __expf(leaky(a1 + ald));
        den += e0 + e1;
        h8_to_f(r0, f0); h8_to_f(r1, f1);
#pragma unroll
        for (int j = 0; j < 8; j++) acc[j] += e0 * f0[j] + e1 * f1[j];
    }
    if (i < end) {
        int s = __ldg(ss_b + i);
        float ew = __expf(leaky(__ldg(alp + (size_t)s * 16 + 12 + h) + ald));
        den += ew;
        uint4 r0 = *((const uint4*)(h_b + (size_t)s * 256) + lane);
        h8_to_f(r0, f0);
#pragma unroll
        for (int j = 0; j < 8; j++) acc[j] += ew * f0[j];
    }
    float inv = 1.f / (den + 1e-16f);

    int c = lane * 8;
    float4 b0 = *(const float4*)(bb + c), b1 = *(const float4*)(bb + c + 4);
    float bv[8] = {b0.x, b0.y, b0.z, b0.w, b1.x, b1.y, b1.z, b1.w};
    float* op = out + (size_t)d * 256 + c;
    float res[8];
#pragma unroll
    for (int j = 0; j < 8; j++) {
        float v = acc[j] * inv + bv[j];
        res[j] = v > 0.f ? v : expm1f(v);
    }
    *(float4*)(op)     = make_float4(res[0], res[1], res[2], res[3]);
    *(float4*)(op + 4) = make_float4(res[4], res[5], res[6], res[7]);
}

// ---------------- host launch ----------------
extern "C" void kernel_launch(void* const* d_in, const int* in_sizes, int n_in,
                              void* d_out, int out_size) {
    const float* x_p  = (const float*)d_in[0];
    const float* x_a  = (const float*)d_in[1];
    const int*   e_c  = (const int*)d_in[2];
    const int*   e_w  = (const int*)d_in[3];
    const int*   e_b  = (const int*)d_in[4];
    const float* W_c  = (const float*)d_in[5];
    const float* as_c = (const float*)d_in[6];
    const float* ad_c = (const float*)d_in[7];
    const float* b_c  = (const float*)d_in[8];
    const float* W_w  = (const float*)d_in[9];
    const float* as_w = (const float*)d_in[10];
    const float* ad_w = (const float*)d_in[11];
    const float* b_w  = (const float*)d_in[12];
    const float* W_b2 = (const float*)d_in[13];
    const float* as_b = (const float*)d_in[14];
    const float* ad_b = (const float*)d_in[15];
    const float* b_b  = (const float*)d_in[16];

    const int np = in_sizes[0] / 256;
    const int na = in_sizes[1] / 256;
    const int Ec = in_sizes[2] / 2;
    const int Ew = in_sizes[3] / 2;
    const int Eb = in_sizes[4] / 2;

    __half* h_base;
    float *alp, *ala, *U;
    int *rp, *ss;
    cudaGetSymbolAddress((void**)&h_base, g_h);
    cudaGetSymbolAddress((void**)&alp, g_al_p);
    cudaGetSymbolAddress((void**)&ala, g_al_a);
    cudaGetSymbolAddress((void**)&U, g_U);
    cudaGetSymbolAddress((void**)&rp, g_rp);
    cudaGetSymbolAddress((void**)&ss, g_ss);

    __half* h_c = h_base;                               // cites src projection (paper)
    __half* h_w = h_base + (size_t)np * 256;            // writes src projection (author)
    __half* h_b = h_base + (size_t)(np + na) * 256;     // wb src projection (paper)
    float* out_p = (float*)d_out;
    float* out_a = out_p + (size_t)np * 256;

    int* rp_c = rp;
    int* rp_w = rp + (NP_MAX + 1);
    int* rp_b = rp + 2 * (NP_MAX + 1);
    int* ss_c = ss;
    int* ss_w = ss + Ec;
    int* ss_b = ss + Ec + Ew;

    // 1. fold attention vectors through W
    prep_u_kernel<<<1, 256>>>(W_c, as_c, ad_c, W_w, as_w, ad_w, W_b2, as_b, ad_b);

    // 2. logit precursors (fp32, exact)
    al_kernel<<<1184, 256>>>(x_p, U,            alp, np, 16);
    al_kernel<<<592,  256>>>(x_a, U + 256 * 16, ala, na, 8);

    // 3. CSR build (fused across relations)
    int cnt_total = 2 * NP_MAX + NA_MAX;
    int Etot = Ec + Ew + Eb;
    zero_cnt_kernel<<<(cnt_total + 255) / 256, 256>>>(cnt_total);
    hist3_kernel<<<(Etot + 255) / 256, 256>>>(e_c, Ec, e_w, Ew, e_b, Eb);
    scan3_kernel<<<3, 1024>>>(np, na, rp);
    scatter3_kernel<<<(Etot + 255) / 256, 256>>>(e_c, Ec, e_w, Ew, e_b, Eb);

    // 4. src projections: tf32 tensor-core GEMMs, fp16 output
    dim3 gp(2, (np + 127) / 128), ga(2, (na + 127) / 128);
    gemm_tf32_kernel<<<gp, 256>>>(x_p, W_c,  h_c, np);
    gemm_tf32_kernel<<<ga, 256>>>(x_a, W_w,  h_w, na);
    gemm_tf32_kernel<<<gp, 256>>>(x_p, W_b2, h_b, np);

    // 5. gather-based aggregation with fused softmax-normalize + bias + ELU
    agg_paper_kernel<<<(np * 32 + 255) / 256, 256>>>(rp_c, ss_c, rp_w, ss_w,
                                                     alp, ala, h_c, h_w,
                                                     b_c, b_w, out_p, np);
    agg_author_kernel<<<(na * 32 + 255) / 256, 256>>>(rp_b, ss_b, alp, ala,
                                                      h_b, b_b, out_a, na);
}

// round 6
// speedup vs baseline: 3.0448x; 1.7918x over previous
#include <cuda_runtime.h>
#include <cuda_fp16.h>
#include <math.h>

#define NP_MAX 100000
#define NA_MAX 50000
#define E_MAX  2100000

// ---------------- device scratch ----------------
__device__ __half g_h[(size_t)(2 * NP_MAX + NA_MAX) * 256]; // h_cites | h_writes | h_wb (fp16)
__device__ float g_al_p[(size_t)NP_MAX * 16];
__device__ float g_al_a[(size_t)NA_MAX * 8];
__device__ float g_U[256 * 16 + 256 * 8];
__device__ int   g_rp[3 * (NP_MAX + 1)];
__device__ int   g_cnt[2 * NP_MAX + NA_MAX];
__device__ int   g_cur[2 * NP_MAX + NA_MAX];
__device__ int   g_ss[E_MAX];

// ---------------- helpers ----------------
__device__ __forceinline__ float leaky(float x) { return x > 0.f ? x : 0.2f * x; }

__device__ __forceinline__ unsigned to_tf32(float f) {
    unsigned u;
    asm("cvt.rna.tf32.f32 %0, %1;" : "=r"(u) : "f"(f));
    return u;
}

__device__ __forceinline__ void mma_tf32(float* c, const unsigned* a, const unsigned* b) {
    asm("mma.sync.aligned.m16n8k8.row.col.f32.tf32.tf32.f32 "
        "{%0,%1,%2,%3},{%4,%5,%6,%7},{%8,%9},{%0,%1,%2,%3};"
        : "+f"(c[0]), "+f"(c[1]), "+f"(c[2]), "+f"(c[3])
        : "r"(a[0]), "r"(a[1]), "r"(a[2]), "r"(a[3]), "r"(b[0]), "r"(b[1]));
}

__device__ __forceinline__ void h8_to_f(uint4 v, float* f) {
    float2 t;
    t = __half22float2(*(__half2*)&v.x); f[0] = t.x; f[1] = t.y;
    t = __half22float2(*(__half2*)&v.y); f[2] = t.x; f[3] = t.y;
    t = __half22float2(*(__half2*)&v.z); f[4] = t.x; f[5] = t.y;
    t = __half22float2(*(__half2*)&v.w); f[6] = t.x; f[7] = t.y;
}

// ---------------- U = W @ a folding ----------------
__global__ void prep_u_kernel(const float* __restrict__ Wc, const float* __restrict__ asc,
                              const float* __restrict__ adc,
                              const float* __restrict__ Ww, const float* __restrict__ asw,
                              const float* __restrict__ adw,
                              const float* __restrict__ Wb, const float* __restrict__ asb,
                              const float* __restrict__ adb) {
    int d = threadIdx.x;
    float* Up = g_U;
    float* Ua = g_U + 256 * 16;
#pragma unroll
    for (int h = 0; h < 4; h++) {
        const float* wc = Wc + d * 256 + h * 64;
        const float* ww = Ww + d * 256 + h * 64;
        const float* wb = Wb + d * 256 + h * 64;
        float s0 = 0.f, s1 = 0.f, s2 = 0.f, s3 = 0.f, s4 = 0.f, s5 = 0.f;
        for (int c = 0; c < 64; c++) {
            s0 += wc[c] * asc[h * 64 + c];
            s1 += wc[c] * adc[h * 64 + c];
            s2 += ww[c] * adw[h * 64 + c];
            s3 += wb[c] * asb[h * 64 + c];
            s4 += ww[c] * asw[h * 64 + c];
            s5 += wb[c] * adb[h * 64 + c];
        }
        Up[d * 16 + 0 + h]  = s0;
        Up[d * 16 + 4 + h]  = s1;
        Up[d * 16 + 8 + h]  = s2;
        Up[d * 16 + 12 + h] = s3;
        Ua[d * 8 + 0 + h]   = s4;
        Ua[d * 8 + 4 + h]   = s5;
    }
}

// ---------------- AL = X @ U, smem-tiled (no shuffles) ----------------
// Block: 256 threads, 32 rows per block. ncols in {16, 8}.
__global__ __launch_bounds__(256) void al_smem_kernel(const float* __restrict__ X,
                                                      const float* __restrict__ U,
                                                      float* __restrict__ AL,
                                                      int N, int ncols) {
    __shared__ float xs[32][257];
    __shared__ float us[256 * 16];
    int tid = threadIdx.x;
    int row0 = blockIdx.x * 32;

    // load U tile (256*ncols floats)
    for (int i = tid; i < 256 * ncols; i += 256) us[i] = U[i];
    // load 32 rows of X (clamp OOB rows to row 0 of the block; stores guarded)
    for (int i = tid; i < 32 * 64; i += 256) {
        int r = i >> 6;             // 0..31
        int c4 = (i & 63) << 2;     // 0..252 step 4
        int gr = row0 + r;
        if (gr >= N) gr = N - 1;
        float4 v = *(const float4*)(X + (size_t)gr * 256 + c4);
        xs[r][c4 + 0] = v.x; xs[r][c4 + 1] = v.y;
        xs[r][c4 + 2] = v.z; xs[r][c4 + 3] = v.w;
    }
    __syncthreads();

    int row = tid & 31;               // lane = row -> conflict-free via 257 padding
    int nper = ncols >> 3;            // 2 (paper) or 1 (author)
    int col0 = (tid >> 5) * nper;
    float s[2] = {0.f, 0.f};
    for (int k = 0; k < 256; k++) {
        float xv = xs[row][k];
#pragma unroll
        for (int q = 0; q < 2; q++)
            if (q < nper) s[q] += xv * us[k * ncols + col0 + q];
    }
    int gr = row0 + row;
    if (gr < N) {
#pragma unroll
        for (int q = 0; q < 2; q++)
            if (q < nper) AL[(size_t)gr * ncols + col0 + q] = s[q];
    }
}

// ---------------- tf32 GEMM (dual-output): C[M,128-tile](fp16) ----------------
// grid.x tiles: [0,1] -> B0/C0 cols 0..255 ; [2,3] -> B1/C1. smem holds tf32 bits.
__global__ __launch_bounds__(256) void gemm_tf32_dual_kernel(
    const float* __restrict__ A,
    const float* __restrict__ B0, const float* __restrict__ B1,
    __half* __restrict__ C0, __half* __restrict__ C1, int M) {
    __shared__ unsigned As[2][16][132];
    __shared__ unsigned Bs[2][16][132];
    const float* B = (blockIdx.x < 2) ? B0 : B1;
    __half* C = (blockIdx.x < 2) ? C0 : C1;
    const int bm = blockIdx.y * 128;
    const int bn = (blockIdx.x & 1) * 128;
    const int tid = threadIdx.x;
    const int wid = tid >> 5, lane = tid & 31;
    const int warpM = wid & 3, warpN = wid >> 2;
    const int row0 = warpM * 32;
    const int nb0  = warpN * 64;
    const int g = lane >> 2, tig = lane & 3;

    float acc[2][8][4];
#pragma unroll
    for (int mi = 0; mi < 2; mi++)
#pragma unroll
        for (int ni = 0; ni < 8; ni++)
#pragma unroll
            for (int r = 0; r < 4; r++) acc[mi][ni][r] = 0.f;

    const int arow0 = tid / 4;
    const int acol  = (tid % 4) * 4;
    const int brow0 = tid / 32;
    const int bcol  = (tid % 32) * 4;

    // preload tile 0 (convert to tf32 at store)
    {
#pragma unroll
        for (int r = 0; r < 2; r++) {
            int row = arow0 + r * 64;
            int grow = bm + row;
            if (grow >= M) grow = M - 1;
            float4 v = *(const float4*)(A + (size_t)grow * 256 + acol);
            As[0][acol + 0][row] = to_tf32(v.x);
            As[0][acol + 1][row] = to_tf32(v.y);
            As[0][acol + 2][row] = to_tf32(v.z);
            As[0][acol + 3][row] = to_tf32(v.w);
        }
#pragma unroll
        for (int r = 0; r < 2; r++) {
            int row = brow0 + r * 8;
            float4 v = *(const float4*)(B + (size_t)row * 256 + bn + bcol);
            Bs[0][row][bcol + 0] = to_tf32(v.x);
            Bs[0][row][bcol + 1] = to_tf32(v.y);
            Bs[0][row][bcol + 2] = to_tf32(v.z);
            Bs[0][row][bcol + 3] = to_tf32(v.w);
        }
    }
    __syncthreads();

    int buf = 0;
    for (int k0 = 16; k0 <= 256; k0 += 16) {
        const bool has_next = (k0 < 256);
        float4 pa[2], pb[2];
        if (has_next) {
#pragma unroll
            for (int r = 0; r < 2; r++) {
                int row = arow0 + r * 64;
                int grow = bm + row;
                if (grow >= M) grow = M - 1;
                pa[r] = *(const float4*)(A + (size_t)grow * 256 + k0 + acol);
            }
#pragma unroll
            for (int r = 0; r < 2; r++) {
                int row = brow0 + r * 8;
                pb[r] = *(const float4*)(B + (size_t)(k0 + row) * 256 + bn + bcol);
            }
        }
#pragma unroll
        for (int ks = 0; ks < 16; ks += 8) {
            unsigned af[2][4];
#pragma unroll
            for (int mi = 0; mi < 2; mi++) {
                int r = row0 + mi * 16 + g;
                af[mi][0] = As[buf][ks + tig][r];
                af[mi][1] = As[buf][ks + tig][r + 8];
                af[mi][2] = As[buf][ks + tig + 4][r];
                af[mi][3] = As[buf][ks + tig + 4][r + 8];
            }
            unsigned bf[8][2];
#pragma unroll
            for (int ni = 0; ni < 8; ni++) {
                int c = nb0 + ni * 8 + g;
                bf[ni][0] = Bs[buf][ks + tig][c];
                bf[ni][1] = Bs[buf][ks + tig + 4][c];
            }
#pragma unroll
            for (int mi = 0; mi < 2; mi++)
#pragma unroll
                for (int ni = 0; ni < 8; ni++)
                    mma_tf32(acc[mi][ni], af[mi], bf[ni]);
        }
        if (has_next) {
            int nbuf = buf ^ 1;
#pragma unroll
            for (int r = 0; r < 2; r++) {
                int row = arow0 + r * 64;
                As[nbuf][acol + 0][row] = to_tf32(pa[r].x);
                As[nbuf][acol + 1][row] = to_tf32(pa[r].y);
                As[nbuf][acol + 2][row] = to_tf32(pa[r].z);
                As[nbuf][acol + 3][row] = to_tf32(pa[r].w);
            }
#pragma unroll
            for (int r = 0; r < 2; r++) {
                int row = brow0 + r * 8;
                Bs[nbuf][row][bcol + 0] = to_tf32(pb[r].x);
                Bs[nbuf][row][bcol + 1] = to_tf32(pb[r].y);
                Bs[nbuf][row][bcol + 2] = to_tf32(pb[r].z);
                Bs[nbuf][row][bcol + 3] = to_tf32(pb[r].w);
            }
            __syncthreads();
            buf = nbuf;
        }
    }

#pragma unroll
    for (int mi = 0; mi < 2; mi++) {
        int row = bm + row0 + mi * 16 + g;
#pragma unroll
        for (int ni = 0; ni < 8; ni++) {
            int col = bn + nb0 + ni * 8 + 2 * tig;
            if (row < M)
                *(__half2*)(C + (size_t)row * 256 + col) =
                    __floats2half2_rn(acc[mi][ni][0], acc[mi][ni][1]);
            if (row + 8 < M)
                *(__half2*)(C + (size_t)(row + 8) * 256 + col) =
                    __floats2half2_rn(acc[mi][ni][2], acc[mi][ni][3]);
        }
    }
}

// ---------------- CSR build ----------------
__global__ void zero_cnt_kernel(int total) {
    int i = blockIdx.x * blockDim.x + threadIdx.x;
    if (i < total) g_cnt[i] = 0;
}

__global__ void hist3_kernel(const int* __restrict__ ec, int Ec,
                             const int* __restrict__ ew, int Ew,
                             const int* __restrict__ eb, int Eb) {
    int t = blockIdx.x * blockDim.x + threadIdx.x;
    if (t < Ec) {
        atomicAdd(&g_cnt[ec[Ec + t]], 1);
    } else if (t < Ec + Ew) {
        int e = t - Ec;
        atomicAdd(&g_cnt[NP_MAX + ew[Ew + e]], 1);
    } else if (t < Ec + Ew + Eb) {
        int e = t - Ec - Ew;
        atomicAdd(&g_cnt[2 * NP_MAX + eb[Eb + e]], 1);
    }
}

__global__ __launch_bounds__(1024) void scan3_kernel(int np, int na, int* __restrict__ rp) {
    int rel = blockIdx.x;
    int n = (rel == 2) ? na : np;
    int off = rel * NP_MAX;
    int* rowptr = rp + rel * (NP_MAX + 1);
    const int* cnt = g_cnt + off;
    int* cursor = g_cur + off;

    __shared__ int sh[1024];
    __shared__ int s_carry;
    int tid = threadIdx.x;
    if (tid == 0) s_carry = 0;
    __syncthreads();
    for (int base = 0; base < n; base += 4096) {
        int idx = base + tid * 4;
        int v0 = (idx + 0 < n) ? cnt[idx + 0] : 0;
        int v1 = (idx + 1 < n) ? cnt[idx + 1] : 0;
        int v2 = (idx + 2 < n) ? cnt[idx + 2] : 0;
        int v3 = (idx + 3 < n) ? cnt[idx + 3] : 0;
        int s = v0 + v1 + v2 + v3;
        sh[tid] = s;
        __syncthreads();
#pragma unroll
        for (int o = 1; o < 1024; o <<= 1) {
            int t = (tid >= o) ? sh[tid - o] : 0;
            __syncthreads();
            sh[tid] += t;
            __syncthreads();
        }
        int carry_in = s_carry;
        int excl = sh[tid] - s + carry_in;
        if (idx + 0 < n) { rowptr[idx + 0] = excl; cursor[idx + 0] = excl; } excl += v0;
        if (idx + 1 < n) { rowptr[idx + 1] = excl; cursor[idx + 1] = excl; } excl += v1;
        if (idx + 2 < n) { rowptr[idx + 2] = excl; cursor[idx + 2] = excl; } excl += v2;
        if (idx + 3 < n) { rowptr[idx + 3] = excl; cursor[idx + 3] = excl; }
        __syncthreads();
        if (tid == 0) s_carry = carry_in + sh[1023];
        __syncthreads();
    }
    if (tid == 0) rowptr[n] = s_carry;
}

__global__ void scatter3_kernel(const int* __restrict__ ec, int Ec,
                                const int* __restrict__ ew, int Ew,
                                const int* __restrict__ eb, int Eb) {
    int t = blockIdx.x * blockDim.x + threadIdx.x;
    if (t < Ec) {
        int pos = atomicAdd(&g_cur[ec[Ec + t]], 1);
        g_ss[pos] = ec[t];
    } else if (t < Ec + Ew) {
        int e = t - Ec;
        int pos = atomicAdd(&g_cur[NP_MAX + ew[Ew + e]], 1);
        g_ss[Ec + pos] = ew[e];
    } else if (t < Ec + Ew + Eb) {
        int e = t - Ec - Ew;
        int pos = atomicAdd(&g_cur[2 * NP_MAX + eb[Eb + e]], 1);
        g_ss[Ec + Ew + pos] = eb[e];
    }
}

// ---------------- aggregation inner loop (unroll-4) ----------------
// als: src precursor base; stride ss; returns den, accumulates into acc[8].
__device__ __forceinline__ float agg_rel(const int* __restrict__ ssrc, int beg, int end,
                                         const float* __restrict__ als, int ss, int hoff,
                                         float ald, const __half* __restrict__ hmat,
                                         int lane, float* acc) {
    float den = 0.f;
    float f0[8], f1[8], f2[8], f3[8];
    int i = beg;
    for (; i + 3 < end; i += 4) {
        int s0 = __ldg(ssrc + i),     s1 = __ldg(ssrc + i + 1);
        int s2 = __ldg(ssrc + i + 2), s3 = __ldg(ssrc + i + 3);
        float a0 = __ldg(als + (size_t)s0 * ss + hoff);
        float a1 = __ldg(als + (size_t)s1 * ss + hoff);
        float a2 = __ldg(als + (size_t)s2 * ss + hoff);
        float a3 = __ldg(als + (size_t)s3 * ss + hoff);
        uint4 r0 = *((const uint4*)(hmat + (size_t)s0 * 256) + lane);
        uint4 r1 = *((const uint4*)(hmat + (size_t)s1 * 256) + lane);
        uint4 r2 = *((const uint4*)(hmat + (size_t)s2 * 256) + lane);
        uint4 r3 = *((const uint4*)(hmat + (size_t)s3 * 256) + lane);
        float e0 = __expf(leaky(a0 + ald));
        float e1 = __expf(leaky(a1 + ald));
        float e2 = __expf(leaky(a2 + ald));
        float e3 = __expf(leaky(a3 + ald));
        den += (e0 + e1) + (e2 + e3);
        h8_to_f(r0, f0); h8_to_f(r1, f1); h8_to_f(r2, f2); h8_to_f(r3, f3);
#pragma unroll
        for (int j = 0; j < 8; j++)
            acc[j] += (e0 * f0[j] + e1 * f1[j]) + (e2 * f2[j] + e3 * f3[j]);
    }
    for (; i < end; i++) {
        int s = __ldg(ssrc + i);
        float ew = __expf(leaky(__ldg(als + (size_t)s * ss + hoff) + ald));
        den += ew;
        uint4 r0 = *((const uint4*)(hmat + (size_t)s * 256) + lane);
        h8_to_f(r0, f0);
#pragma unroll
        for (int j = 0; j < 8; j++) acc[j] += ew * f0[j];
    }
    return den;
}

// ---------------- paper aggregation: cites + writes, fused ----------------
__global__ __launch_bounds__(256) void agg_paper_kernel(
    const int* __restrict__ rp_c, const int* __restrict__ ss_c,
    const int* __restrict__ rp_w, const int* __restrict__ ss_w,
    const float* __restrict__ alp, const float* __restrict__ ala,
    const __half* __restrict__ h_c, const __half* __restrict__ h_w,
    const float* __restrict__ bc, const float* __restrict__ bw,
    float* __restrict__ out, int np)
{
    int d = (blockIdx.x * blockDim.x + threadIdx.x) >> 5;
    if (d >= np) return;
    int lane = threadIdx.x & 31;
    int h = lane >> 3;

    float acc[8] = {0.f, 0.f, 0.f, 0.f, 0.f, 0.f, 0.f, 0.f};
    float res[8];

    // cites: dst alp[d*16+4+h], src alp[s*16+0+h]
    {
        float ald = __ldg(alp + (size_t)d * 16 + 4 + h);
        float den = agg_rel(ss_c, rp_c[d], rp_c[d + 1], alp, 16, h, ald, h_c, lane, acc);
        float inv = 1.f / (den + 1e-16f);
#pragma unroll
        for (int j = 0; j < 8; j++) { res[j] = acc[j] * inv; acc[j] = 0.f; }
    }
    // writes: dst alp[d*16+8+h], src ala[s*8+0+h]
    {
        float ald = __ldg(alp + (size_t)d * 16 + 8 + h);
        float den = agg_rel(ss_w, rp_w[d], rp_w[d + 1], ala, 8, h, ald, h_w, lane, acc);
        float inv = 1.f / (den + 1e-16f);
#pragma unroll
        for (int j = 0; j < 8; j++) res[j] += acc[j] * inv;
    }

    int c = lane * 8;
    float4 b0c = *(const float4*)(bc + c), b1c = *(const float4*)(bc + c + 4);
    float4 b0w = *(const float4*)(bw + c), b1w = *(const float4*)(bw + c + 4);
    float bb[8] = {b0c.x + b0w.x, b0c.y + b0w.y, b0c.z + b0w.z, b0c.w + b0w.w,
                   b1c.x + b1w.x, b1c.y + b1w.y, b1c.z + b1w.z, b1c.w + b1w.w};
    float* op = out + (size_t)d * 256 + c;
#pragma unroll
    for (int j = 0; j < 8; j++) {
        float v = res[j] + bb[j];
        res[j] = v > 0.f ? v : expm1f(v);
    }
    *(float4*)(op)     = make_float4(res[0], res[1], res[2], res[3]);
    *(float4*)(op + 4) = make_float4(res[4], res[5], res[6], res[7]);
}

// ---------------- author aggregation: wb ----------------
__global__ __launch_bounds__(256) void agg_author_kernel(
    const int* __restrict__ rp_b, const int* __restrict__ ss_b,
    const float* __restrict__ alp, const float* __restrict__ ala,
    const __half* __restrict__ h_b, const float* __restrict__ bb,
    float* __restrict__ out, int na)
{
    int d = (blockIdx.x * blockDim.x + threadIdx.x) >> 5;
    if (d >= na) return;
    int lane = threadIdx.x & 31;
    int h = lane >> 3;

    float acc[8] = {0.f, 0.f, 0.f, 0.f, 0.f, 0.f, 0.f, 0.f};
    float ald = __ldg(ala + (size_t)d * 8 + 4 + h);
    float den = agg_rel(ss_b, rp_b[d], rp_b[d + 1], alp, 16, 12 + h, ald, h_b, lane, acc);
    float inv = 1.f / (den + 1e-16f);

    int c = lane * 8;
    float4 b0 = *(const float4*)(bb + c), b1 = *(const float4*)(bb + c + 4);
    float bv[8] = {b0.x, b0.y, b0.z, b0.w, b1.x, b1.y, b1.z, b1.w};
    float* op = out + (size_t)d * 256 + c;
    float res[8];
#pragma unroll
    for (int j = 0; j < 8; j++) {
        float v = acc[j] * inv + bv[j];
        res[j] = v > 0.f ? v : expm1f(v);
    }
    *(float4*)(op)     = make_float4(res[0], res[1], res[2], res[3]);
    *(float4*)(op + 4) = make_float4(res[4], res[5], res[6], res[7]);
}

// ---------------- host launch ----------------
extern "C" void kernel_launch(void* const* d_in, const int* in_sizes, int n_in,
                              void* d_out, int out_size) {
    const float* x_p  = (const float*)d_in[0];
    const float* x_a  = (const float*)d_in[1];
    const int*   e_c  = (const int*)d_in[2];
    const int*   e_w  = (const int*)d_in[3];
    const int*   e_b  = (const int*)d_in[4];
    const float* W_c  = (const float*)d_in[5];
    const float* as_c = (const float*)d_in[6];
    const float* ad_c = (const float*)d_in[7];
    const float* b_c  = (const float*)d_in[8];
    const float* W_w  = (const float*)d_in[9];
    const float* as_w = (const float*)d_in[10];
    const float* ad_w = (const float*)d_in[11];
    const float* b_w  = (const float*)d_in[12];
    const float* W_b2 = (const float*)d_in[13];
    const float* as_b = (const float*)d_in[14];
    const float* ad_b = (const float*)d_in[15];
    const float* b_b  = (const float*)d_in[16];

    const int np = in_sizes[0] / 256;
    const int na = in_sizes[1] / 256;
    const int Ec = in_sizes[2] / 2;
    const int Ew = in_sizes[3] / 2;
    const int Eb = in_sizes[4] / 2;

    __half* h_base;
    float *alp, *ala, *U;
    int *rp, *ss;
    cudaGetSymbolAddress((void**)&h_base, g_h);
    cudaGetSymbolAddress((void**)&alp, g_al_p);
    cudaGetSymbolAddress((void**)&ala, g_al_a);
    cudaGetSymbolAddress((void**)&U, g_U);
    cudaGetSymbolAddress((void**)&rp, g_rp);
    cudaGetSymbolAddress((void**)&ss, g_ss);

    __half* h_c = h_base;
    __half* h_w = h_base + (size_t)np * 256;
    __half* h_b = h_base + (size_t)(np + na) * 256;
    float* out_p = (float*)d_out;
    float* out_a = out_p + (size_t)np * 256;

    int* rp_c = rp;
    int* rp_w = rp + (NP_MAX + 1);
    int* rp_b = rp + 2 * (NP_MAX + 1);
    int* ss_c = ss;
    int* ss_w = ss + Ec;
    int* ss_b = ss + Ec + Ew;

    // 1. fold attention vectors through W
    prep_u_kernel<<<1, 256>>>(W_c, as_c, ad_c, W_w, as_w, ad_w, W_b2, as_b, ad_b);

    // 2. logit precursors (fp32, exact)
    al_smem_kernel<<<(np + 31) / 32, 256>>>(x_p, U,            alp, np, 16);
    al_smem_kernel<<<(na + 31) / 32, 256>>>(x_a, U + 256 * 16, ala, na, 8);

    // 3. CSR build
    int cnt_total = 2 * NP_MAX + NA_MAX;
    int Etot = Ec + Ew + Eb;
    zero_cnt_kernel<<<(cnt_total + 255) / 256, 256>>>(cnt_total);
    hist3_kernel<<<(Etot + 255) / 256, 256>>>(e_c, Ec, e_w, Ew, e_b, Eb);
    scan3_kernel<<<3, 1024>>>(np, na, rp);
    scatter3_kernel<<<(Etot + 255) / 256, 256>>>(e_c, Ec, e_w, Ew, e_b, Eb);

    // 4. projections: fused dual GEMM for paper (h_c + h_b), single for author
    dim3 gp(4, (np + 127) / 128), ga(2, (na + 127) / 128);
    gemm_tf32_dual_kernel<<<gp, 256>>>(x_p, W_c, W_b2, h_c, h_b, np);
    gemm_tf32_dual_kernel<<<ga, 256>>>(x_a, W_w, W_w, h_w, h_w, na);

    // 5. gather aggregation, fused softmax-normalize + bias + ELU
    agg_paper_kernel<<<(np * 32 + 255) / 256, 256>>>(rp_c, ss_c, rp_w, ss_w,
                                                     alp, ala, h_c, h_w,
                                                     b_c, b_w, out_p, np);
    agg_author_kernel<<<(na * 32 + 255) / 256, 256>>>(rp_b, ss_b, alp, ala,
                                                      h_b, b_b, out_a, na);
}